// round 2
// baseline (speedup 1.0000x reference)
#include <cuda_runtime.h>
#include <cuda_bf16.h>
#include <mma.h>
#include <cstdint>

using namespace nvcuda;

#define B_   4
#define T_   2048
#define C_   1024
#define H_   16
#define D_   64
#define M_   (B_*T_)      /* 8192 */
#define N1_  (3*C_)       /* 3072 */

// ---------------- scratch (device globals) -------------------------------------
__device__ __nv_bfloat16 g_xhi [M_*C_];
__device__ __nv_bfloat16 g_xlo [M_*C_];
__device__ __nv_bfloat16 g_wkqvhi[C_*N1_];
__device__ __nv_bfloat16 g_wkqvlo[C_*N1_];
__device__ __nv_bfloat16 g_wouthi[C_*C_];
__device__ __nv_bfloat16 g_woutlo[C_*C_];
__device__ __nv_bfloat16 g_q  [M_*C_];
__device__ __nv_bfloat16 g_k  [M_*C_];
__device__ __nv_bfloat16 g_vhi[M_*C_];
__device__ __nv_bfloat16 g_vlo[M_*C_];
__device__ __nv_bfloat16 g_atthi[M_*C_];
__device__ __nv_bfloat16 g_attlo[M_*C_];
__device__ float         g_stage[M_*N1_];

// ---------------- fp32 -> (bf16 hi, bf16 lo) split -----------------------------
__global__ void cvt_split(const float4* __restrict__ in,
                          __nv_bfloat16* __restrict__ hi,
                          __nv_bfloat16* __restrict__ lo, int n4) {
    int i = blockIdx.x * blockDim.x + threadIdx.x;
    if (i >= n4) return;
    float4 v = in[i];
    __nv_bfloat16 h[4], l[4];
    float vv[4] = {v.x, v.y, v.z, v.w};
    #pragma unroll
    for (int j = 0; j < 4; j++) {
        h[j] = __float2bfloat16_rn(vv[j]);
        l[j] = __float2bfloat16_rn(vv[j] - __bfloat162float(h[j]));
    }
    *(uint2*)&hi[4*i] = *(uint2*)h;
    *(uint2*)&lo[4*i] = *(uint2*)l;
}

// ---------------- 3-term compensated bf16 GEMM ---------------------------------
// C = (Ahi+Alo)(Bhi+Blo) ~= Ahi*Bhi + Ahi*Blo + Alo*Bhi   (fp32 accum)
#define BM 128
#define BN 128
#define BK 32

__global__ void __launch_bounds__(256)
gemm_bf16_split(const __nv_bfloat16* __restrict__ Ahi,
                const __nv_bfloat16* __restrict__ Alo,
                const __nv_bfloat16* __restrict__ Bhi,
                const __nv_bfloat16* __restrict__ Blo,
                float* __restrict__ Cm, int N, int K) {
    __shared__ __align__(16) __nv_bfloat16 sAh[BM][BK + 8];
    __shared__ __align__(16) __nv_bfloat16 sAl[BM][BK + 8];
    __shared__ __align__(16) __nv_bfloat16 sBh[BK][BN + 8];
    __shared__ __align__(16) __nv_bfloat16 sBl[BK][BN + 8];

    const int bn = blockIdx.x * BN;
    const int bm = blockIdx.y * BM;
    const int tid  = threadIdx.x;
    const int warp = tid >> 5;
    const int wm = (warp >> 2) * 64;
    const int wn = (warp & 3) * 32;

    wmma::fragment<wmma::accumulator, 16,16,16, float> acc[4][2];
    #pragma unroll
    for (int i = 0; i < 4; i++)
        #pragma unroll
        for (int j = 0; j < 2; j++) wmma::fill_fragment(acc[i][j], 0.0f);

    for (int k0 = 0; k0 < K; k0 += BK) {
        #pragma unroll
        for (int t = 0; t < 2; t++) {
            int idx = tid + t*256;
            int r = idx >> 2, c = (idx & 3) * 8;
            size_t src = (size_t)(bm + r)*K + k0 + c;
            *(uint4*)&sAh[r][c] = *(const uint4*)&Ahi[src];
            *(uint4*)&sAl[r][c] = *(const uint4*)&Alo[src];
        }
        #pragma unroll
        for (int t = 0; t < 2; t++) {
            int idx = tid + t*256;
            int r = idx >> 4, c = (idx & 15) * 8;
            size_t src = (size_t)(k0 + r)*N + bn + c;
            *(uint4*)&sBh[r][c] = *(const uint4*)&Bhi[src];
            *(uint4*)&sBl[r][c] = *(const uint4*)&Blo[src];
        }
        __syncthreads();

        #pragma unroll
        for (int kk = 0; kk < BK; kk += 16) {
            wmma::fragment<wmma::matrix_a, 16,16,16, __nv_bfloat16, wmma::row_major> ah[4], al[4];
            wmma::fragment<wmma::matrix_b, 16,16,16, __nv_bfloat16, wmma::row_major> bh[2], bl[2];
            #pragma unroll
            for (int i = 0; i < 4; i++) {
                wmma::load_matrix_sync(ah[i], &sAh[wm + i*16][kk], BK + 8);
                wmma::load_matrix_sync(al[i], &sAl[wm + i*16][kk], BK + 8);
            }
            #pragma unroll
            for (int j = 0; j < 2; j++) {
                wmma::load_matrix_sync(bh[j], &sBh[kk][wn + j*16], BN + 8);
                wmma::load_matrix_sync(bl[j], &sBl[kk][wn + j*16], BN + 8);
            }
            #pragma unroll
            for (int i = 0; i < 4; i++)
                #pragma unroll
                for (int j = 0; j < 2; j++) {
                    wmma::mma_sync(acc[i][j], ah[i], bh[j], acc[i][j]);
                    wmma::mma_sync(acc[i][j], ah[i], bl[j], acc[i][j]);
                    wmma::mma_sync(acc[i][j], al[i], bh[j], acc[i][j]);
                }
        }
        __syncthreads();
    }
    #pragma unroll
    for (int i = 0; i < 4; i++)
        #pragma unroll
        for (int j = 0; j < 2; j++)
            wmma::store_matrix_sync(&Cm[(size_t)(bm + wm + i*16)*N + bn + wn + j*16],
                                    acc[i][j], N, wmma::mem_row_major);
}

// ---------------- bias + scatter kqv -> head-major q/k (bf16), v (hi+lo) -------
// source split order is k, q, v. Fold 1/32 softmax scale into q.
__global__ void scatter_kqv(const float* __restrict__ stage,
                            const float* __restrict__ b_kqv) {
    int i = blockIdx.x * blockDim.x + threadIdx.x;       // over (M_*N1_)/2
    if (i >= (M_*N1_)/2) return;
    int idx = i * 2;
    int m = idx / N1_, n = idx % N1_;
    float v0 = stage[idx]     + b_kqv[n];
    float v1 = stage[idx + 1] + b_kqv[n + 1];
    int third = n >> 10;
    int c = n & 1023;
    int h = c >> 6, dd = c & 63;
    int b = m >> 11, t = m & (T_ - 1);
    size_t dst = (((size_t)(b*H_ + h))*T_ + t)*D_ + dd;
    if (third == 0) {
        *(__nv_bfloat162*)&g_k[dst] = __floats2bfloat162_rn(v0, v1);
    } else if (third == 1) {
        *(__nv_bfloat162*)&g_q[dst] = __floats2bfloat162_rn(v0*(1.f/32.f), v1*(1.f/32.f));
    } else {
        __nv_bfloat16 h0 = __float2bfloat16_rn(v0);
        __nv_bfloat16 h1 = __float2bfloat16_rn(v1);
        __nv_bfloat16 l0 = __float2bfloat16_rn(v0 - __bfloat162float(h0));
        __nv_bfloat16 l1 = __float2bfloat16_rn(v1 - __bfloat162float(h1));
        __nv_bfloat162 ph; ph.x = h0; ph.y = h1;
        __nv_bfloat162 pl; pl.x = l0; pl.y = l1;
        *(__nv_bfloat162*)&g_vhi[dst] = ph;
        *(__nv_bfloat162*)&g_vlo[dst] = pl;
    }
}

// ---------------- attention (FA-2, mma.m16n8k16.bf16, compensated PV) ----------
__device__ __forceinline__ void mma16816(float c[4], const uint32_t a[4],
                                         uint32_t b0, uint32_t b1) {
    asm volatile(
        "mma.sync.aligned.m16n8k16.row.col.f32.bf16.bf16.f32 "
        "{%0,%1,%2,%3}, {%4,%5,%6,%7}, {%8,%9}, {%0,%1,%2,%3};\n"
        : "+f"(c[0]), "+f"(c[1]), "+f"(c[2]), "+f"(c[3])
        : "r"(a[0]), "r"(a[1]), "r"(a[2]), "r"(a[3]), "r"(b0), "r"(b1));
}

__device__ __forceinline__ uint32_t pack_bf16(float x, float y) {
    __nv_bfloat162 t = __floats2bfloat162_rn(x, y);
    return *(uint32_t*)&t;
}

#define KST 72
#define VST 68

__global__ void __launch_bounds__(128)
attn_kernel(const __nv_bfloat16* __restrict__ Qg,
            const __nv_bfloat16* __restrict__ Kg,
            const __nv_bfloat16* __restrict__ Vhig,
            const __nv_bfloat16* __restrict__ Vlog,
            __nv_bfloat16* __restrict__ Ohi,
            __nv_bfloat16* __restrict__ Olo) {
    __shared__ __align__(16) __nv_bfloat16 sQ  [64*KST];
    __shared__ __align__(16) __nv_bfloat16 sK  [64*KST];
    __shared__ __align__(16) __nv_bfloat16 sVth[64*VST];
    __shared__ __align__(16) __nv_bfloat16 sVtl[64*VST];

    const int qt  = blockIdx.x;
    const int bh  = blockIdx.y;
    const int b   = bh >> 4, h = bh & 15;
    const int tid = threadIdx.x;
    const int warp = tid >> 5, lane = tid & 31;
    const int g  = lane >> 2;
    const int tg = lane & 3;

    const __nv_bfloat16* Qb  = Qg   + (size_t)bh * T_ * D_;
    const __nv_bfloat16* Kb  = Kg   + (size_t)bh * T_ * D_;
    const __nv_bfloat16* Vhb = Vhig + (size_t)bh * T_ * D_;
    const __nv_bfloat16* Vlb = Vlog + (size_t)bh * T_ * D_;
    const int qb = qt * 64;

    #pragma unroll
    for (int t = 0; t < 4; t++) {
        int idx = tid + t*128;
        int r = idx >> 3, c = (idx & 7) * 8;
        *(uint4*)&sQ[r*KST + c] = *(const uint4*)&Qb[(size_t)(qb + r)*D_ + c];
    }
    __syncthreads();

    uint32_t qa[4][4];
    {
        int r0 = warp*16 + g;
        #pragma unroll
        for (int kk = 0; kk < 4; kk++) {
            int cb = kk*16 + tg*2;
            qa[kk][0] = *(uint32_t*)&sQ[r0*KST + cb];
            qa[kk][1] = *(uint32_t*)&sQ[(r0+8)*KST + cb];
            qa[kk][2] = *(uint32_t*)&sQ[r0*KST + cb + 8];
            qa[kk][3] = *(uint32_t*)&sQ[(r0+8)*KST + cb + 8];
        }
    }

    float o[8][4];
    #pragma unroll
    for (int i = 0; i < 8; i++) { o[i][0]=o[i][1]=o[i][2]=o[i][3]=0.f; }
    float m0 = -1e30f, m1 = -1e30f, l0 = 0.f, l1 = 0.f;

    const int ntiles = qt + 1;
    for (int it = 0; it < ntiles; it++) {
        const int kb = it * 64;
        __syncthreads();
        #pragma unroll
        for (int t = 0; t < 4; t++) {                     // K tile 64x64
            int idx = tid + t*128;
            int r = idx >> 3, c = (idx & 7) * 8;
            *(uint4*)&sK[r*KST + c] = *(const uint4*)&Kb[(size_t)(kb + r)*D_ + c];
        }
        #pragma unroll
        for (int t = 0; t < 4; t++) {                     // V hi+lo, transposed
            int idx = tid + t*128;
            int r = idx >> 3, c0 = (idx & 7) * 8;
            uint4 vh = *(const uint4*)&Vhb[(size_t)(kb + r)*D_ + c0];
            uint4 vl = *(const uint4*)&Vlb[(size_t)(kb + r)*D_ + c0];
            __nv_bfloat16 th[8], tl[8];
            *(uint4*)th = vh; *(uint4*)tl = vl;
            #pragma unroll
            for (int i = 0; i < 8; i++) {
                sVth[(c0 + i)*VST + r] = th[i];
                sVtl[(c0 + i)*VST + r] = tl[i];
            }
        }
        __syncthreads();

        // S = Q @ K^T (plain bf16; scale folded into q)
        float s[8][4];
        #pragma unroll
        for (int nt = 0; nt < 8; nt++) { s[nt][0]=s[nt][1]=s[nt][2]=s[nt][3]=0.f; }
        #pragma unroll
        for (int kk = 0; kk < 4; kk++)
            #pragma unroll
            for (int nt = 0; nt < 8; nt++) {
                uint32_t b0 = *(uint32_t*)&sK[(nt*8 + g)*KST + kk*16 + tg*2];
                uint32_t b1 = *(uint32_t*)&sK[(nt*8 + g)*KST + kk*16 + tg*2 + 8];
                mma16816(s[nt], qa[kk], b0, b1);
            }

        if (it == ntiles - 1) {   // causal mask on diagonal tile
            int qg0 = qb + warp*16 + g;
            #pragma unroll
            for (int nt = 0; nt < 8; nt++) {
                int kg = kb + nt*8 + tg*2;
                if (kg     > qg0    ) s[nt][0] = -1e30f;
                if (kg + 1 > qg0    ) s[nt][1] = -1e30f;
                if (kg     > qg0 + 8) s[nt][2] = -1e30f;
                if (kg + 1 > qg0 + 8) s[nt][3] = -1e30f;
            }
        }

        // online softmax
        float mx0 = -1e30f, mx1 = -1e30f;
        #pragma unroll
        for (int nt = 0; nt < 8; nt++) {
            mx0 = fmaxf(mx0, fmaxf(s[nt][0], s[nt][1]));
            mx1 = fmaxf(mx1, fmaxf(s[nt][2], s[nt][3]));
        }
        #pragma unroll
        for (int off = 1; off < 4; off <<= 1) {
            mx0 = fmaxf(mx0, __shfl_xor_sync(0xffffffffu, mx0, off));
            mx1 = fmaxf(mx1, __shfl_xor_sync(0xffffffffu, mx1, off));
        }
        float nm0 = fmaxf(m0, mx0), nm1 = fmaxf(m1, mx1);
        float a0 = __expf(m0 - nm0), a1 = __expf(m1 - nm1);
        float sum0 = 0.f, sum1 = 0.f;
        #pragma unroll
        for (int nt = 0; nt < 8; nt++) {
            s[nt][0] = __expf(s[nt][0] - nm0);
            s[nt][1] = __expf(s[nt][1] - nm0);
            s[nt][2] = __expf(s[nt][2] - nm1);
            s[nt][3] = __expf(s[nt][3] - nm1);
            sum0 += s[nt][0] + s[nt][1];
            sum1 += s[nt][2] + s[nt][3];
        }
        #pragma unroll
        for (int off = 1; off < 4; off <<= 1) {
            sum0 += __shfl_xor_sync(0xffffffffu, sum0, off);
            sum1 += __shfl_xor_sync(0xffffffffu, sum1, off);
        }
        l0 = l0*a0 + sum0;  l1 = l1*a1 + sum1;
        m0 = nm0;           m1 = nm1;
        #pragma unroll
        for (int nt = 0; nt < 8; nt++) {
            o[nt][0] *= a0; o[nt][1] *= a0; o[nt][2] *= a1; o[nt][3] *= a1;
        }

        // P split into hi+lo (registers, identity remap S-accum -> A-frag)
        uint32_t ph[4][4], pl[4][4];
        #pragma unroll
        for (int kt = 0; kt < 4; kt++) {
            #pragma unroll
            for (int half = 0; half < 2; half++) {
                float x0 = s[2*kt + half][0], x1 = s[2*kt + half][1];
                float y0 = s[2*kt + half][2], y1 = s[2*kt + half][3];
                // row pair (c0,c1)
                __nv_bfloat16 hx0 = __float2bfloat16_rn(x0);
                __nv_bfloat16 hx1 = __float2bfloat16_rn(x1);
                __nv_bfloat162 hp; hp.x = hx0; hp.y = hx1;
                ph[kt][2*half] = *(uint32_t*)&hp;
                __nv_bfloat162 lp;
                lp.x = __float2bfloat16_rn(x0 - __bfloat162float(hx0));
                lp.y = __float2bfloat16_rn(x1 - __bfloat162float(hx1));
                pl[kt][2*half] = *(uint32_t*)&lp;
                // row pair (c2,c3)
                __nv_bfloat16 hy0 = __float2bfloat16_rn(y0);
                __nv_bfloat16 hy1 = __float2bfloat16_rn(y1);
                __nv_bfloat162 hq; hq.x = hy0; hq.y = hy1;
                ph[kt][2*half + 1] = *(uint32_t*)&hq;
                __nv_bfloat162 lq;
                lq.x = __float2bfloat16_rn(y0 - __bfloat162float(hy0));
                lq.y = __float2bfloat16_rn(y1 - __bfloat162float(hy1));
                pl[kt][2*half + 1] = *(uint32_t*)&lq;
            }
        }
        #pragma unroll
        for (int kt = 0; kt < 4; kt++)
            #pragma unroll
            for (int nt = 0; nt < 8; nt++) {
                int off = (nt*8 + g)*VST + kt*16 + tg*2;
                uint32_t bh0 = *(uint32_t*)&sVth[off];
                uint32_t bh1 = *(uint32_t*)&sVth[off + 8];
                uint32_t bl0 = *(uint32_t*)&sVtl[off];
                uint32_t bl1 = *(uint32_t*)&sVtl[off + 8];
                mma16816(o[nt], ph[kt], bh0, bh1);
                mma16816(o[nt], ph[kt], bl0, bl1);
                mma16816(o[nt], pl[kt], bh0, bh1);
            }
    }

    // epilogue: O/l -> att hi+lo at [b, t, h*64+dd]
    float inv0 = 1.f / l0, inv1 = 1.f / l1;
    int r0 = qb + warp*16 + g;
    #pragma unroll
    for (int nt = 0; nt < 8; nt++) {
        int dd = nt*8 + tg*2;
        float v00 = o[nt][0]*inv0, v01 = o[nt][1]*inv0;
        float v10 = o[nt][2]*inv1, v11 = o[nt][3]*inv1;
        size_t d0 = ((size_t)b*T_ + r0    )*C_ + h*D_ + dd;
        size_t d1 = ((size_t)b*T_ + r0 + 8)*C_ + h*D_ + dd;
        __nv_bfloat16 h00 = __float2bfloat16_rn(v00);
        __nv_bfloat16 h01 = __float2bfloat16_rn(v01);
        __nv_bfloat16 h10 = __float2bfloat16_rn(v10);
        __nv_bfloat16 h11 = __float2bfloat16_rn(v11);
        __nv_bfloat162 a0; a0.x = h00; a0.y = h01;
        __nv_bfloat162 a1; a1.x = h10; a1.y = h11;
        __nv_bfloat162 b0;
        b0.x = __float2bfloat16_rn(v00 - __bfloat162float(h00));
        b0.y = __float2bfloat16_rn(v01 - __bfloat162float(h01));
        __nv_bfloat162 b1;
        b1.x = __float2bfloat16_rn(v10 - __bfloat162float(h10));
        b1.y = __float2bfloat16_rn(v11 - __bfloat162float(h11));
        *(__nv_bfloat162*)&Ohi[d0] = a0;
        *(__nv_bfloat162*)&Ohi[d1] = a1;
        *(__nv_bfloat162*)&Olo[d0] = b0;
        *(__nv_bfloat162*)&Olo[d1] = b1;
    }
}

// ---------------- final bias add ------------------------------------------------
__global__ void add_bias_out(const float* __restrict__ stage,
                             const float* __restrict__ bias,
                             float* __restrict__ out) {
    int i = blockIdx.x * blockDim.x + threadIdx.x;
    if (i >= (M_*C_)/4) return;
    int idx = i * 4;
    float4 v = *(const float4*)&stage[idx];
    float4 bb = *(const float4*)&bias[idx & (C_ - 1)];
    v.x += bb.x; v.y += bb.y; v.z += bb.z; v.w += bb.w;
    *(float4*)&out[idx] = v;
}

// ---------------- launch --------------------------------------------------------
extern "C" void kernel_launch(void* const* d_in, const int* in_sizes, int n_in,
                              void* d_out, int out_size) {
    const float* x      = (const float*)d_in[0];
    const float* W_kqv  = (const float*)d_in[1];
    const float* b_kqv  = (const float*)d_in[2];
    const float* W_out  = (const float*)d_in[3];
    const float* b_out  = (const float*)d_in[4];
    float*       out    = (float*)d_out;

    __nv_bfloat16 *p_xhi, *p_xlo, *p_wkqvhi, *p_wkqvlo, *p_wouthi, *p_woutlo;
    __nv_bfloat16 *p_q, *p_k, *p_vhi, *p_vlo, *p_atthi, *p_attlo;
    float *p_stage;
    cudaGetSymbolAddress((void**)&p_xhi,    g_xhi);
    cudaGetSymbolAddress((void**)&p_xlo,    g_xlo);
    cudaGetSymbolAddress((void**)&p_wkqvhi, g_wkqvhi);
    cudaGetSymbolAddress((void**)&p_wkqvlo, g_wkqvlo);
    cudaGetSymbolAddress((void**)&p_wouthi, g_wouthi);
    cudaGetSymbolAddress((void**)&p_woutlo, g_woutlo);
    cudaGetSymbolAddress((void**)&p_q,      g_q);
    cudaGetSymbolAddress((void**)&p_k,      g_k);
    cudaGetSymbolAddress((void**)&p_vhi,    g_vhi);
    cudaGetSymbolAddress((void**)&p_vlo,    g_vlo);
    cudaGetSymbolAddress((void**)&p_atthi,  g_atthi);
    cudaGetSymbolAddress((void**)&p_attlo,  g_attlo);
    cudaGetSymbolAddress((void**)&p_stage,  g_stage);

    // 1) split converts
    cvt_split<<<(M_*C_/4 + 255)/256, 256>>>((const float4*)x,     p_xhi,    p_xlo,    M_*C_/4);
    cvt_split<<<(C_*N1_/4 + 255)/256, 256>>>((const float4*)W_kqv, p_wkqvhi, p_wkqvlo, C_*N1_/4);
    cvt_split<<<(C_*C_/4 + 255)/256, 256>>>((const float4*)W_out, p_wouthi, p_woutlo, C_*C_/4);

    // 2) kqv GEMM (compensated): [8192,1024] x [1024,3072]
    {
        dim3 grid(N1_/BN, M_/BM);
        gemm_bf16_split<<<grid, 256>>>(p_xhi, p_xlo, p_wkqvhi, p_wkqvlo, p_stage, N1_, C_);
    }

    // 3) bias + scatter (k,q plain; v hi+lo; 1/32 folded into q)
    scatter_kqv<<<(M_*N1_/2 + 255)/256, 256>>>(p_stage, b_kqv);

    // 4) attention (compensated PV)
    {
        dim3 grid(T_/64, B_*H_);
        attn_kernel<<<grid, 128>>>(p_q, p_k, p_vhi, p_vlo, p_atthi, p_attlo);
    }

    // 5) output projection GEMM (compensated): [8192,1024] x [1024,1024]
    {
        dim3 grid(C_/BN, M_/BM);
        gemm_bf16_split<<<grid, 256>>>(p_atthi, p_attlo, p_wouthi, p_woutlo, p_stage, C_, C_);
    }

    // 6) bias -> d_out
    add_bias_out<<<(M_*C_/4 + 255)/256, 256>>>(p_stage, b_out, out);

    (void)in_sizes; (void)n_in; (void)out_size;
}

// round 3
// speedup vs baseline: 1.0819x; 1.0819x over previous
#include <cuda_runtime.h>
#include <cuda_bf16.h>
#include <mma.h>
#include <cstdint>

using namespace nvcuda;

#define B_   4
#define T_   2048
#define C_   1024
#define H_   16
#define D_   64
#define M_   (B_*T_)      /* 8192 */
#define N1_  (3*C_)       /* 3072 */

// ---------------- scratch (device globals) -------------------------------------
__device__ __nv_bfloat16 g_xhi [M_*C_];
__device__ __nv_bfloat16 g_xlo [M_*C_];
__device__ __nv_bfloat16 g_wkqvhi[C_*N1_];
__device__ __nv_bfloat16 g_wkqvlo[C_*N1_];
__device__ __nv_bfloat16 g_wouthi[C_*C_];
__device__ __nv_bfloat16 g_woutlo[C_*C_];
__device__ __nv_bfloat16 g_q  [M_*C_];
__device__ __nv_bfloat16 g_k  [M_*C_];
__device__ __nv_bfloat16 g_vhi[M_*C_];
__device__ __nv_bfloat16 g_vlo[M_*C_];
__device__ __nv_bfloat16 g_atthi[M_*C_];
__device__ __nv_bfloat16 g_attlo[M_*C_];
__device__ float         g_stage[M_*N1_];

// ---------------- cp.async helpers ---------------------------------------------
__device__ __forceinline__ void cp16(void* smem, const void* gmem) {
    uint32_t s = (uint32_t)__cvta_generic_to_shared(smem);
    asm volatile("cp.async.cg.shared.global [%0], [%1], 16;\n" :: "r"(s), "l"(gmem));
}
__device__ __forceinline__ void cp_commit() {
    asm volatile("cp.async.commit_group;\n");
}
template <int N>
__device__ __forceinline__ void cp_wait() {
    asm volatile("cp.async.wait_group %0;\n" :: "n"(N));
}

// ---------------- fp32 -> (bf16 hi, bf16 lo) split -----------------------------
__global__ void cvt_split(const float4* __restrict__ in,
                          __nv_bfloat16* __restrict__ hi,
                          __nv_bfloat16* __restrict__ lo, int n4) {
    int i = blockIdx.x * blockDim.x + threadIdx.x;
    if (i >= n4) return;
    float4 v = in[i];
    __nv_bfloat16 h[4], l[4];
    float vv[4] = {v.x, v.y, v.z, v.w};
    #pragma unroll
    for (int j = 0; j < 4; j++) {
        h[j] = __float2bfloat16_rn(vv[j]);
        l[j] = __float2bfloat16_rn(vv[j] - __bfloat162float(h[j]));
    }
    *(uint2*)&hi[4*i] = *(uint2*)h;
    *(uint2*)&lo[4*i] = *(uint2*)l;
}

// ---------------- 3-term compensated bf16 GEMM, cp.async double-buffered -------
// C = Ahi*Bhi + Ahi*Blo + Alo*Bhi   (fp32 accum)
#define BM 128
#define BN 128
#define BK 32
#define ASTR (BK + 8)    /* 40 elems, 80B rows (16B aligned) */
#define BSTR (BN + 8)    /* 136 elems, 272B rows */

struct Stage {
    __nv_bfloat16 Ah[BM*ASTR];
    __nv_bfloat16 Al[BM*ASTR];
    __nv_bfloat16 Bh[BK*BSTR];
    __nv_bfloat16 Bl[BK*BSTR];
};
#define SMEM_BYTES (2 * (int)sizeof(Stage))

__global__ void __launch_bounds__(256)
gemm_bf16_split(const __nv_bfloat16* __restrict__ Ahi,
                const __nv_bfloat16* __restrict__ Alo,
                const __nv_bfloat16* __restrict__ Bhi,
                const __nv_bfloat16* __restrict__ Blo,
                float* __restrict__ Cm, int N, int K) {
    extern __shared__ __align__(16) char smem_raw[];
    Stage* stg = reinterpret_cast<Stage*>(smem_raw);

    const int bn = blockIdx.x * BN;
    const int bm = blockIdx.y * BM;
    const int tid  = threadIdx.x;
    const int warp = tid >> 5;
    const int wm = (warp >> 2) * 64;
    const int wn = (warp & 3) * 32;

    // per-thread load coordinates (constant across stages)
    const int ar0 = tid >> 2,        ac0 = (tid & 3) * 8;          // A row/col, t=0
    const int br0 = tid >> 4,        bc0 = (tid & 15) * 8;         // B row/col, t=0

    auto load_stage = [&](Stage& S, int k0) {
        #pragma unroll
        for (int t = 0; t < 2; t++) {
            int r = ar0 + t*64, c = ac0;
            size_t src = (size_t)(bm + r)*K + k0 + c;
            cp16(&S.Ah[r*ASTR + c], &Ahi[src]);
            cp16(&S.Al[r*ASTR + c], &Alo[src]);
        }
        #pragma unroll
        for (int t = 0; t < 2; t++) {
            int r = br0 + t*16, c = bc0;
            size_t src = (size_t)(k0 + r)*N + bn + c;
            cp16(&S.Bh[r*BSTR + c], &Bhi[src]);
            cp16(&S.Bl[r*BSTR + c], &Blo[src]);
        }
        cp_commit();
    };

    wmma::fragment<wmma::accumulator, 16,16,16, float> acc[4][2];
    #pragma unroll
    for (int i = 0; i < 4; i++)
        #pragma unroll
        for (int j = 0; j < 2; j++) wmma::fill_fragment(acc[i][j], 0.0f);

    const int NIT = K / BK;
    load_stage(stg[0], 0);

    for (int it = 0; it < NIT; it++) {
        if (it + 1 < NIT) {
            load_stage(stg[(it + 1) & 1], (it + 1) * BK);
            cp_wait<1>();
        } else {
            cp_wait<0>();
        }
        __syncthreads();

        Stage& S = stg[it & 1];
        #pragma unroll
        for (int kk = 0; kk < BK; kk += 16) {
            wmma::fragment<wmma::matrix_a, 16,16,16, __nv_bfloat16, wmma::row_major> ah[4], al[4];
            wmma::fragment<wmma::matrix_b, 16,16,16, __nv_bfloat16, wmma::row_major> bh[2], bl[2];
            #pragma unroll
            for (int i = 0; i < 4; i++) {
                wmma::load_matrix_sync(ah[i], &S.Ah[(wm + i*16)*ASTR + kk], ASTR);
                wmma::load_matrix_sync(al[i], &S.Al[(wm + i*16)*ASTR + kk], ASTR);
            }
            #pragma unroll
            for (int j = 0; j < 2; j++) {
                wmma::load_matrix_sync(bh[j], &S.Bh[kk*BSTR + wn + j*16], BSTR);
                wmma::load_matrix_sync(bl[j], &S.Bl[kk*BSTR + wn + j*16], BSTR);
            }
            #pragma unroll
            for (int i = 0; i < 4; i++)
                #pragma unroll
                for (int j = 0; j < 2; j++) {
                    wmma::mma_sync(acc[i][j], ah[i], bh[j], acc[i][j]);
                    wmma::mma_sync(acc[i][j], ah[i], bl[j], acc[i][j]);
                    wmma::mma_sync(acc[i][j], al[i], bh[j], acc[i][j]);
                }
        }
        __syncthreads();
    }
    #pragma unroll
    for (int i = 0; i < 4; i++)
        #pragma unroll
        for (int j = 0; j < 2; j++)
            wmma::store_matrix_sync(&Cm[(size_t)(bm + wm + i*16)*N + bn + wn + j*16],
                                    acc[i][j], N, wmma::mem_row_major);
}

// ---------------- bias + scatter kqv -> head-major q/k (bf16), v (hi+lo) -------
// source split order is k, q, v. Fold 1/32 softmax scale into q.
__global__ void scatter_kqv(const float* __restrict__ stage,
                            const float* __restrict__ b_kqv) {
    int i = blockIdx.x * blockDim.x + threadIdx.x;       // over (M_*N1_)/2
    if (i >= (M_*N1_)/2) return;
    int idx = i * 2;
    int m = idx / N1_, n = idx % N1_;
    float v0 = stage[idx]     + b_kqv[n];
    float v1 = stage[idx + 1] + b_kqv[n + 1];
    int third = n >> 10;
    int c = n & 1023;
    int h = c >> 6, dd = c & 63;
    int b = m >> 11, t = m & (T_ - 1);
    size_t dst = (((size_t)(b*H_ + h))*T_ + t)*D_ + dd;
    if (third == 0) {
        *(__nv_bfloat162*)&g_k[dst] = __floats2bfloat162_rn(v0, v1);
    } else if (third == 1) {
        *(__nv_bfloat162*)&g_q[dst] = __floats2bfloat162_rn(v0*(1.f/32.f), v1*(1.f/32.f));
    } else {
        __nv_bfloat16 h0 = __float2bfloat16_rn(v0);
        __nv_bfloat16 h1 = __float2bfloat16_rn(v1);
        __nv_bfloat16 l0 = __float2bfloat16_rn(v0 - __bfloat162float(h0));
        __nv_bfloat16 l1 = __float2bfloat16_rn(v1 - __bfloat162float(h1));
        __nv_bfloat162 ph; ph.x = h0; ph.y = h1;
        __nv_bfloat162 pl; pl.x = l0; pl.y = l1;
        *(__nv_bfloat162*)&g_vhi[dst] = ph;
        *(__nv_bfloat162*)&g_vlo[dst] = pl;
    }
}

// ---------------- attention (FA-2, mma.m16n8k16.bf16, compensated PV) ----------
__device__ __forceinline__ void mma16816(float c[4], const uint32_t a[4],
                                         uint32_t b0, uint32_t b1) {
    asm volatile(
        "mma.sync.aligned.m16n8k16.row.col.f32.bf16.bf16.f32 "
        "{%0,%1,%2,%3}, {%4,%5,%6,%7}, {%8,%9}, {%0,%1,%2,%3};\n"
        : "+f"(c[0]), "+f"(c[1]), "+f"(c[2]), "+f"(c[3])
        : "r"(a[0]), "r"(a[1]), "r"(a[2]), "r"(a[3]), "r"(b0), "r"(b1));
}

#define KST 72
#define VST 68

__global__ void __launch_bounds__(128)
attn_kernel(const __nv_bfloat16* __restrict__ Qg,
            const __nv_bfloat16* __restrict__ Kg,
            const __nv_bfloat16* __restrict__ Vhig,
            const __nv_bfloat16* __restrict__ Vlog,
            __nv_bfloat16* __restrict__ Ohi,
            __nv_bfloat16* __restrict__ Olo) {
    __shared__ __align__(16) __nv_bfloat16 sQ  [64*KST];
    __shared__ __align__(16) __nv_bfloat16 sK  [64*KST];
    __shared__ __align__(16) __nv_bfloat16 sVth[64*VST];
    __shared__ __align__(16) __nv_bfloat16 sVtl[64*VST];

    const int qt  = blockIdx.x;
    const int bh  = blockIdx.y;
    const int b   = bh >> 4, h = bh & 15;
    const int tid = threadIdx.x;
    const int warp = tid >> 5, lane = tid & 31;
    const int g  = lane >> 2;
    const int tg = lane & 3;

    const __nv_bfloat16* Qb  = Qg   + (size_t)bh * T_ * D_;
    const __nv_bfloat16* Kb  = Kg   + (size_t)bh * T_ * D_;
    const __nv_bfloat16* Vhb = Vhig + (size_t)bh * T_ * D_;
    const __nv_bfloat16* Vlb = Vlog + (size_t)bh * T_ * D_;
    const int qb = qt * 64;

    #pragma unroll
    for (int t = 0; t < 4; t++) {
        int idx = tid + t*128;
        int r = idx >> 3, c = (idx & 7) * 8;
        *(uint4*)&sQ[r*KST + c] = *(const uint4*)&Qb[(size_t)(qb + r)*D_ + c];
    }
    __syncthreads();

    uint32_t qa[4][4];
    {
        int r0 = warp*16 + g;
        #pragma unroll
        for (int kk = 0; kk < 4; kk++) {
            int cb = kk*16 + tg*2;
            qa[kk][0] = *(uint32_t*)&sQ[r0*KST + cb];
            qa[kk][1] = *(uint32_t*)&sQ[(r0+8)*KST + cb];
            qa[kk][2] = *(uint32_t*)&sQ[r0*KST + cb + 8];
            qa[kk][3] = *(uint32_t*)&sQ[(r0+8)*KST + cb + 8];
        }
    }

    float o[8][4];
    #pragma unroll
    for (int i = 0; i < 8; i++) { o[i][0]=o[i][1]=o[i][2]=o[i][3]=0.f; }
    float m0 = -1e30f, m1 = -1e30f, l0 = 0.f, l1 = 0.f;

    const int ntiles = qt + 1;
    for (int it = 0; it < ntiles; it++) {
        const int kb = it * 64;
        __syncthreads();
        #pragma unroll
        for (int t = 0; t < 4; t++) {                     // K tile 64x64
            int idx = tid + t*128;
            int r = idx >> 3, c = (idx & 7) * 8;
            *(uint4*)&sK[r*KST + c] = *(const uint4*)&Kb[(size_t)(kb + r)*D_ + c];
        }
        #pragma unroll
        for (int t = 0; t < 4; t++) {                     // V hi+lo, transposed
            int idx = tid + t*128;
            int r = idx >> 3, c0 = (idx & 7) * 8;
            uint4 vh = *(const uint4*)&Vhb[(size_t)(kb + r)*D_ + c0];
            uint4 vl = *(const uint4*)&Vlb[(size_t)(kb + r)*D_ + c0];
            __nv_bfloat16 th[8], tl[8];
            *(uint4*)th = vh; *(uint4*)tl = vl;
            #pragma unroll
            for (int i = 0; i < 8; i++) {
                sVth[(c0 + i)*VST + r] = th[i];
                sVtl[(c0 + i)*VST + r] = tl[i];
            }
        }
        __syncthreads();

        // S = Q @ K^T (plain bf16; scale folded into q)
        float s[8][4];
        #pragma unroll
        for (int nt = 0; nt < 8; nt++) { s[nt][0]=s[nt][1]=s[nt][2]=s[nt][3]=0.f; }
        #pragma unroll
        for (int kk = 0; kk < 4; kk++)
            #pragma unroll
            for (int nt = 0; nt < 8; nt++) {
                uint32_t b0 = *(uint32_t*)&sK[(nt*8 + g)*KST + kk*16 + tg*2];
                uint32_t b1 = *(uint32_t*)&sK[(nt*8 + g)*KST + kk*16 + tg*2 + 8];
                mma16816(s[nt], qa[kk], b0, b1);
            }

        if (it == ntiles - 1) {   // causal mask on diagonal tile
            int qg0 = qb + warp*16 + g;
            #pragma unroll
            for (int nt = 0; nt < 8; nt++) {
                int kg = kb + nt*8 + tg*2;
                if (kg     > qg0    ) s[nt][0] = -1e30f;
                if (kg + 1 > qg0    ) s[nt][1] = -1e30f;
                if (kg     > qg0 + 8) s[nt][2] = -1e30f;
                if (kg + 1 > qg0 + 8) s[nt][3] = -1e30f;
            }
        }

        // online softmax
        float mx0 = -1e30f, mx1 = -1e30f;
        #pragma unroll
        for (int nt = 0; nt < 8; nt++) {
            mx0 = fmaxf(mx0, fmaxf(s[nt][0], s[nt][1]));
            mx1 = fmaxf(mx1, fmaxf(s[nt][2], s[nt][3]));
        }
        #pragma unroll
        for (int off = 1; off < 4; off <<= 1) {
            mx0 = fmaxf(mx0, __shfl_xor_sync(0xffffffffu, mx0, off));
            mx1 = fmaxf(mx1, __shfl_xor_sync(0xffffffffu, mx1, off));
        }
        float nm0 = fmaxf(m0, mx0), nm1 = fmaxf(m1, mx1);
        float a0 = __expf(m0 - nm0), a1 = __expf(m1 - nm1);
        float sum0 = 0.f, sum1 = 0.f;
        #pragma unroll
        for (int nt = 0; nt < 8; nt++) {
            s[nt][0] = __expf(s[nt][0] - nm0);
            s[nt][1] = __expf(s[nt][1] - nm0);
            s[nt][2] = __expf(s[nt][2] - nm1);
            s[nt][3] = __expf(s[nt][3] - nm1);
            sum0 += s[nt][0] + s[nt][1];
            sum1 += s[nt][2] + s[nt][3];
        }
        #pragma unroll
        for (int off = 1; off < 4; off <<= 1) {
            sum0 += __shfl_xor_sync(0xffffffffu, sum0, off);
            sum1 += __shfl_xor_sync(0xffffffffu, sum1, off);
        }
        l0 = l0*a0 + sum0;  l1 = l1*a1 + sum1;
        m0 = nm0;           m1 = nm1;
        #pragma unroll
        for (int nt = 0; nt < 8; nt++) {
            o[nt][0] *= a0; o[nt][1] *= a0; o[nt][2] *= a1; o[nt][3] *= a1;
        }

        // P split into hi+lo (registers, identity remap S-accum -> A-frag)
        uint32_t ph[4][4], pl[4][4];
        #pragma unroll
        for (int kt = 0; kt < 4; kt++) {
            #pragma unroll
            for (int half = 0; half < 2; half++) {
                float x0 = s[2*kt + half][0], x1 = s[2*kt + half][1];
                float y0 = s[2*kt + half][2], y1 = s[2*kt + half][3];
                __nv_bfloat16 hx0 = __float2bfloat16_rn(x0);
                __nv_bfloat16 hx1 = __float2bfloat16_rn(x1);
                __nv_bfloat162 hp; hp.x = hx0; hp.y = hx1;
                ph[kt][2*half] = *(uint32_t*)&hp;
                __nv_bfloat162 lp;
                lp.x = __float2bfloat16_rn(x0 - __bfloat162float(hx0));
                lp.y = __float2bfloat16_rn(x1 - __bfloat162float(hx1));
                pl[kt][2*half] = *(uint32_t*)&lp;
                __nv_bfloat16 hy0 = __float2bfloat16_rn(y0);
                __nv_bfloat16 hy1 = __float2bfloat16_rn(y1);
                __nv_bfloat162 hq; hq.x = hy0; hq.y = hy1;
                ph[kt][2*half + 1] = *(uint32_t*)&hq;
                __nv_bfloat162 lq;
                lq.x = __float2bfloat16_rn(y0 - __bfloat162float(hy0));
                lq.y = __float2bfloat16_rn(y1 - __bfloat162float(hy1));
                pl[kt][2*half + 1] = *(uint32_t*)&lq;
            }
        }
        #pragma unroll
        for (int kt = 0; kt < 4; kt++)
            #pragma unroll
            for (int nt = 0; nt < 8; nt++) {
                int off = (nt*8 + g)*VST + kt*16 + tg*2;
                uint32_t bh0 = *(uint32_t*)&sVth[off];
                uint32_t bh1 = *(uint32_t*)&sVth[off + 8];
                uint32_t bl0 = *(uint32_t*)&sVtl[off];
                uint32_t bl1 = *(uint32_t*)&sVtl[off + 8];
                mma16816(o[nt], ph[kt], bh0, bh1);
                mma16816(o[nt], ph[kt], bl0, bl1);
                mma16816(o[nt], pl[kt], bh0, bh1);
            }
    }

    // epilogue: O/l -> att hi+lo at [b, t, h*64+dd]
    float inv0 = 1.f / l0, inv1 = 1.f / l1;
    int r0 = qb + warp*16 + g;
    #pragma unroll
    for (int nt = 0; nt < 8; nt++) {
        int dd = nt*8 + tg*2;
        float v00 = o[nt][0]*inv0, v01 = o[nt][1]*inv0;
        float v10 = o[nt][2]*inv1, v11 = o[nt][3]*inv1;
        size_t d0 = ((size_t)b*T_ + r0    )*C_ + h*D_ + dd;
        size_t d1 = ((size_t)b*T_ + r0 + 8)*C_ + h*D_ + dd;
        __nv_bfloat16 h00 = __float2bfloat16_rn(v00);
        __nv_bfloat16 h01 = __float2bfloat16_rn(v01);
        __nv_bfloat16 h10 = __float2bfloat16_rn(v10);
        __nv_bfloat16 h11 = __float2bfloat16_rn(v11);
        __nv_bfloat162 a0; a0.x = h00; a0.y = h01;
        __nv_bfloat162 a1; a1.x = h10; a1.y = h11;
        __nv_bfloat162 b0;
        b0.x = __float2bfloat16_rn(v00 - __bfloat162float(h00));
        b0.y = __float2bfloat16_rn(v01 - __bfloat162float(h01));
        __nv_bfloat162 b1;
        b1.x = __float2bfloat16_rn(v10 - __bfloat162float(h10));
        b1.y = __float2bfloat16_rn(v11 - __bfloat162float(h11));
        *(__nv_bfloat162*)&Ohi[d0] = a0;
        *(__nv_bfloat162*)&Ohi[d1] = a1;
        *(__nv_bfloat162*)&Olo[d0] = b0;
        *(__nv_bfloat162*)&Olo[d1] = b1;
    }
}

// ---------------- final bias add ------------------------------------------------
__global__ void add_bias_out(const float* __restrict__ stage,
                             const float* __restrict__ bias,
                             float* __restrict__ out) {
    int i = blockIdx.x * blockDim.x + threadIdx.x;
    if (i >= (M_*C_)/4) return;
    int idx = i * 4;
    float4 v = *(const float4*)&stage[idx];
    float4 bb = *(const float4*)&bias[idx & (C_ - 1)];
    v.x += bb.x; v.y += bb.y; v.z += bb.z; v.w += bb.w;
    *(float4*)&out[idx] = v;
}

// ---------------- launch --------------------------------------------------------
extern "C" void kernel_launch(void* const* d_in, const int* in_sizes, int n_in,
                              void* d_out, int out_size) {
    const float* x      = (const float*)d_in[0];
    const float* W_kqv  = (const float*)d_in[1];
    const float* b_kqv  = (const float*)d_in[2];
    const float* W_out  = (const float*)d_in[3];
    const float* b_out  = (const float*)d_in[4];
    float*       out    = (float*)d_out;

    __nv_bfloat16 *p_xhi, *p_xlo, *p_wkqvhi, *p_wkqvlo, *p_wouthi, *p_woutlo;
    __nv_bfloat16 *p_q, *p_k, *p_vhi, *p_vlo, *p_atthi, *p_attlo;
    float *p_stage;
    cudaGetSymbolAddress((void**)&p_xhi,    g_xhi);
    cudaGetSymbolAddress((void**)&p_xlo,    g_xlo);
    cudaGetSymbolAddress((void**)&p_wkqvhi, g_wkqvhi);
    cudaGetSymbolAddress((void**)&p_wkqvlo, g_wkqvlo);
    cudaGetSymbolAddress((void**)&p_wouthi, g_wouthi);
    cudaGetSymbolAddress((void**)&p_woutlo, g_woutlo);
    cudaGetSymbolAddress((void**)&p_q,      g_q);
    cudaGetSymbolAddress((void**)&p_k,      g_k);
    cudaGetSymbolAddress((void**)&p_vhi,    g_vhi);
    cudaGetSymbolAddress((void**)&p_vlo,    g_vlo);
    cudaGetSymbolAddress((void**)&p_atthi,  g_atthi);
    cudaGetSymbolAddress((void**)&p_attlo,  g_attlo);
    cudaGetSymbolAddress((void**)&p_stage,  g_stage);

    cudaFuncSetAttribute(gemm_bf16_split,
                         cudaFuncAttributeMaxDynamicSharedMemorySize, SMEM_BYTES);

    // 1) split converts
    cvt_split<<<(M_*C_/4 + 255)/256, 256>>>((const float4*)x,     p_xhi,    p_xlo,    M_*C_/4);
    cvt_split<<<(C_*N1_/4 + 255)/256, 256>>>((const float4*)W_kqv, p_wkqvhi, p_wkqvlo, C_*N1_/4);
    cvt_split<<<(C_*C_/4 + 255)/256, 256>>>((const float4*)W_out, p_wouthi, p_woutlo, C_*C_/4);

    // 2) kqv GEMM (compensated): [8192,1024] x [1024,3072]
    {
        dim3 grid(N1_/BN, M_/BM);
        gemm_bf16_split<<<grid, 256, SMEM_BYTES>>>(p_xhi, p_xlo, p_wkqvhi, p_wkqvlo,
                                                   p_stage, N1_, C_);
    }

    // 3) bias + scatter (k,q plain; v hi+lo; 1/32 folded into q)
    scatter_kqv<<<(M_*N1_/2 + 255)/256, 256>>>(p_stage, b_kqv);

    // 4) attention (compensated PV)
    {
        dim3 grid(T_/64, B_*H_);
        attn_kernel<<<grid, 128>>>(p_q, p_k, p_vhi, p_vlo, p_atthi, p_attlo);
    }

    // 5) output projection GEMM (compensated): [8192,1024] x [1024,1024]
    {
        dim3 grid(C_/BN, M_/BM);
        gemm_bf16_split<<<grid, 256, SMEM_BYTES>>>(p_atthi, p_attlo, p_wouthi, p_woutlo,
                                                   p_stage, C_, C_);
    }

    // 6) bias -> d_out
    add_bias_out<<<(M_*C_/4 + 255)/256, 256>>>(p_stage, b_out, out);

    (void)in_sizes; (void)n_in; (void)out_size;
}

// round 5
// speedup vs baseline: 2.3870x; 2.2062x over previous
#include <cuda_runtime.h>
#include <cuda_fp16.h>
#include <mma.h>
#include <cstdint>

using namespace nvcuda;

#define B_   4
#define T_   2048
#define C_   1024
#define H_   16
#define D_   64
#define M_   (B_*T_)      /* 8192 */
#define N1_  (3*C_)       /* 3072 */

// ---------------- scratch (device globals) -------------------------------------
__device__ __half g_xh  [M_*C_];
__device__ __half g_wkqv[C_*N1_];
__device__ __half g_wout[C_*C_];
__device__ __half g_q   [M_*C_];
__device__ __half g_k   [M_*C_];
__device__ __half g_v   [M_*C_];
__device__ __half g_att [M_*C_];
__device__ float  g_stage[M_*N1_];

// ---------------- cp.async helpers ---------------------------------------------
__device__ __forceinline__ void cp16(void* smem, const void* gmem) {
    uint32_t s = (uint32_t)__cvta_generic_to_shared(smem);
    asm volatile("cp.async.cg.shared.global [%0], [%1], 16;\n" :: "r"(s), "l"(gmem));
}
__device__ __forceinline__ void cp_commit() {
    asm volatile("cp.async.commit_group;\n");
}
template <int N>
__device__ __forceinline__ void cp_wait() {
    asm volatile("cp.async.wait_group %0;\n" :: "n"(N));
}

// ---------------- fp32 -> fp16 convert (vectorized x4) -------------------------
__global__ void cvt4(const float4* __restrict__ in,
                     __half2* __restrict__ out, int n4) {
    int i = blockIdx.x * blockDim.x + threadIdx.x;
    if (i < n4) {
        float4 v = in[i];
        out[2*i]   = __floats2half2_rn(v.x, v.y);
        out[2*i+1] = __floats2half2_rn(v.z, v.w);
    }
}

// ---------------- fp16 GEMM, cp.async double-buffered, 64x64 warp tile ---------
#define BM 128
#define BN 256
#define BK 32
#define ASTR (BK + 8)    /* 40 halfs, 80B rows */
#define BSTR (BN + 8)    /* 264 halfs, 528B rows (%16B == 0) */

struct Stage {
    __half A[BM*ASTR];
    __half Bm[BK*BSTR];
};
#define SMEM_BYTES (2 * (int)sizeof(Stage))

__global__ void __launch_bounds__(256)
gemm_fp16(const __half* __restrict__ Ag,
          const __half* __restrict__ Bg,
          float* __restrict__ Cm, int N, int K) {
    extern __shared__ __align__(16) char smem_raw[];
    Stage* stg = reinterpret_cast<Stage*>(smem_raw);

    const int bn = blockIdx.x * BN;
    const int bm = blockIdx.y * BM;
    const int tid  = threadIdx.x;
    const int warp = tid >> 5;
    const int wm = (warp >> 2) * 64;   // 2 warps along M
    const int wn = (warp & 3) * 64;    // 4 warps along N

    auto load_stage = [&](Stage& S, int k0) {
        #pragma unroll
        for (int t = 0; t < 2; t++) {           // A: 128x32 halfs = 512 cp16
            int idx = tid + t*256;
            int r = idx >> 2, c = (idx & 3) * 8;
            cp16(&S.A[r*ASTR + c], &Ag[(size_t)(bm + r)*K + k0 + c]);
        }
        #pragma unroll
        for (int t = 0; t < 4; t++) {           // B: 32x256 halfs = 1024 cp16
            int idx = tid + t*256;
            int r = idx >> 5, c = (idx & 31) * 8;
            cp16(&S.Bm[r*BSTR + c], &Bg[(size_t)(k0 + r)*N + bn + c]);
        }
        cp_commit();
    };

    wmma::fragment<wmma::accumulator, 16,16,16, float> acc[4][4];
    #pragma unroll
    for (int i = 0; i < 4; i++)
        #pragma unroll
        for (int j = 0; j < 4; j++) wmma::fill_fragment(acc[i][j], 0.0f);

    const int NIT = K / BK;
    load_stage(stg[0], 0);

    for (int it = 0; it < NIT; it++) {
        if (it + 1 < NIT) {
            load_stage(stg[(it + 1) & 1], (it + 1) * BK);
            cp_wait<1>();
        } else {
            cp_wait<0>();
        }
        __syncthreads();

        Stage& S = stg[it & 1];
        #pragma unroll
        for (int kk = 0; kk < BK; kk += 16) {
            wmma::fragment<wmma::matrix_a, 16,16,16, __half, wmma::row_major> af[4];
            wmma::fragment<wmma::matrix_b, 16,16,16, __half, wmma::row_major> bf[4];
            #pragma unroll
            for (int i = 0; i < 4; i++)
                wmma::load_matrix_sync(af[i], &S.A[(wm + i*16)*ASTR + kk], ASTR);
            #pragma unroll
            for (int j = 0; j < 4; j++)
                wmma::load_matrix_sync(bf[j], &S.Bm[kk*BSTR + wn + j*16], BSTR);
            #pragma unroll
            for (int i = 0; i < 4; i++)
                #pragma unroll
                for (int j = 0; j < 4; j++)
                    wmma::mma_sync(acc[i][j], af[i], bf[j], acc[i][j]);
        }
        __syncthreads();
    }
    #pragma unroll
    for (int i = 0; i < 4; i++)
        #pragma unroll
        for (int j = 0; j < 4; j++)
            wmma::store_matrix_sync(&Cm[(size_t)(bm + wm + i*16)*N + bn + wn + j*16],
                                    acc[i][j], N, wmma::mem_row_major);
}

// ---------------- bias + scatter kqv -> head-major fp16 q/k/v ------------------
// source split order is k, q, v. Fold 1/32 softmax scale into q.
__global__ void scatter_kqv(const float* __restrict__ stage,
                            const float* __restrict__ b_kqv) {
    int i = blockIdx.x * blockDim.x + threadIdx.x;       // over (M_*N1_)/2
    if (i >= (M_*N1_)/2) return;
    int idx = i * 2;
    int m = idx / N1_, n = idx % N1_;
    float v0 = stage[idx]     + b_kqv[n];
    float v1 = stage[idx + 1] + b_kqv[n + 1];
    int third = n >> 10;
    int c = n & 1023;
    int h = c >> 6, dd = c & 63;
    int b = m >> 11, t = m & (T_ - 1);
    size_t dst = (((size_t)(b*H_ + h))*T_ + t)*D_ + dd;
    if (third == 1) { v0 *= (1.0f/32.0f); v1 *= (1.0f/32.0f); }
    __half2 pv = __floats2half2_rn(v0, v1);
    if      (third == 0) *(__half2*)&g_k[dst] = pv;
    else if (third == 1) *(__half2*)&g_q[dst] = pv;
    else                 *(__half2*)&g_v[dst] = pv;
}

// ---------------- attention (FA-2, mma.m16n8k16.f16) ---------------------------
__device__ __forceinline__ void mma16816(float c[4], const uint32_t a[4],
                                         uint32_t b0, uint32_t b1) {
    asm volatile(
        "mma.sync.aligned.m16n8k16.row.col.f32.f16.f16.f32 "
        "{%0,%1,%2,%3}, {%4,%5,%6,%7}, {%8,%9}, {%0,%1,%2,%3};\n"
        : "+f"(c[0]), "+f"(c[1]), "+f"(c[2]), "+f"(c[3])
        : "r"(a[0]), "r"(a[1]), "r"(a[2]), "r"(a[3]), "r"(b0), "r"(b1));
}

__device__ __forceinline__ uint32_t pack_h2(float x, float y) {
    __half2 t = __floats2half2_rn(x, y);
    return *(uint32_t*)&t;
}

#define KST 72
#define VST 68

__global__ void __launch_bounds__(128)
attn_kernel(const __half* __restrict__ Qg,
            const __half* __restrict__ Kg,
            const __half* __restrict__ Vg,
            __half* __restrict__ Og) {
    __shared__ __align__(16) __half sQ [64*KST];
    __shared__ __align__(16) __half sK [64*KST];
    __shared__ __align__(16) __half sVt[64*VST];

    const int qt  = blockIdx.x;
    const int bh  = blockIdx.y;
    const int b   = bh >> 4, h = bh & 15;
    const int tid = threadIdx.x;
    const int warp = tid >> 5, lane = tid & 31;
    const int g  = lane >> 2;
    const int tg = lane & 3;

    const __half* Qb = Qg + (size_t)bh * T_ * D_;
    const __half* Kb = Kg + (size_t)bh * T_ * D_;
    const __half* Vb = Vg + (size_t)bh * T_ * D_;
    const int qb = qt * 64;

    #pragma unroll
    for (int t = 0; t < 4; t++) {
        int idx = tid + t*128;
        int r = idx >> 3, c = (idx & 7) * 8;
        *(uint4*)&sQ[r*KST + c] = *(const uint4*)&Qb[(size_t)(qb + r)*D_ + c];
    }
    __syncthreads();

    uint32_t qa[4][4];
    {
        int r0 = warp*16 + g;
        #pragma unroll
        for (int kk = 0; kk < 4; kk++) {
            int cb = kk*16 + tg*2;
            qa[kk][0] = *(uint32_t*)&sQ[r0*KST + cb];
            qa[kk][1] = *(uint32_t*)&sQ[(r0+8)*KST + cb];
            qa[kk][2] = *(uint32_t*)&sQ[r0*KST + cb + 8];
            qa[kk][3] = *(uint32_t*)&sQ[(r0+8)*KST + cb + 8];
        }
    }

    float o[8][4];
    #pragma unroll
    for (int i = 0; i < 8; i++) { o[i][0]=o[i][1]=o[i][2]=o[i][3]=0.f; }
    float m0 = -1e30f, m1 = -1e30f, l0 = 0.f, l1 = 0.f;

    const int ntiles = qt + 1;
    for (int it = 0; it < ntiles; it++) {
        const int kb = it * 64;
        __syncthreads();
        #pragma unroll
        for (int t = 0; t < 4; t++) {                     // K tile 64x64
            int idx = tid + t*128;
            int r = idx >> 3, c = (idx & 7) * 8;
            *(uint4*)&sK[r*KST + c] = *(const uint4*)&Kb[(size_t)(kb + r)*D_ + c];
        }
        #pragma unroll
        for (int t = 0; t < 4; t++) {                     // V tile, transposed
            int idx = tid + t*128;
            int r = idx >> 3, c0 = (idx & 7) * 8;
            uint4 vv = *(const uint4*)&Vb[(size_t)(kb + r)*D_ + c0];
            __half tmp[8];
            *(uint4*)tmp = vv;
            #pragma unroll
            for (int i = 0; i < 8; i++) sVt[(c0 + i)*VST + r] = tmp[i];
        }
        __syncthreads();

        // S = Q @ K^T (scale folded into q)
        float s[8][4];
        #pragma unroll
        for (int nt = 0; nt < 8; nt++) { s[nt][0]=s[nt][1]=s[nt][2]=s[nt][3]=0.f; }
        #pragma unroll
        for (int kk = 0; kk < 4; kk++)
            #pragma unroll
            for (int nt = 0; nt < 8; nt++) {
                uint32_t b0 = *(uint32_t*)&sK[(nt*8 + g)*KST + kk*16 + tg*2];
                uint32_t b1 = *(uint32_t*)&sK[(nt*8 + g)*KST + kk*16 + tg*2 + 8];
                mma16816(s[nt], qa[kk], b0, b1);
            }

        if (it == ntiles - 1) {   // causal mask on diagonal tile
            int qg0 = qb + warp*16 + g;
            #pragma unroll
            for (int nt = 0; nt < 8; nt++) {
                int kg = kb + nt*8 + tg*2;
                if (kg     > qg0    ) s[nt][0] = -1e30f;
                if (kg + 1 > qg0    ) s[nt][1] = -1e30f;
                if (kg     > qg0 + 8) s[nt][2] = -1e30f;
                if (kg + 1 > qg0 + 8) s[nt][3] = -1e30f;
            }
        }

        // online softmax
        float mx0 = -1e30f, mx1 = -1e30f;
        #pragma unroll
        for (int nt = 0; nt < 8; nt++) {
            mx0 = fmaxf(mx0, fmaxf(s[nt][0], s[nt][1]));
            mx1 = fmaxf(mx1, fmaxf(s[nt][2], s[nt][3]));
        }
        #pragma unroll
        for (int off = 1; off < 4; off <<= 1) {
            mx0 = fmaxf(mx0, __shfl_xor_sync(0xffffffffu, mx0, off));
            mx1 = fmaxf(mx1, __shfl_xor_sync(0xffffffffu, mx1, off));
        }
        float nm0 = fmaxf(m0, mx0), nm1 = fmaxf(m1, mx1);
        float a0 = __expf(m0 - nm0), a1 = __expf(m1 - nm1);
        float sum0 = 0.f, sum1 = 0.f;
        #pragma unroll
        for (int nt = 0; nt < 8; nt++) {
            s[nt][0] = __expf(s[nt][0] - nm0);
            s[nt][1] = __expf(s[nt][1] - nm0);
            s[nt][2] = __expf(s[nt][2] - nm1);
            s[nt][3] = __expf(s[nt][3] - nm1);
            sum0 += s[nt][0] + s[nt][1];
            sum1 += s[nt][2] + s[nt][3];
        }
        #pragma unroll
        for (int off = 1; off < 4; off <<= 1) {
            sum0 += __shfl_xor_sync(0xffffffffu, sum0, off);
            sum1 += __shfl_xor_sync(0xffffffffu, sum1, off);
        }
        l0 = l0*a0 + sum0;  l1 = l1*a1 + sum1;
        m0 = nm0;           m1 = nm1;
        #pragma unroll
        for (int nt = 0; nt < 8; nt++) {
            o[nt][0] *= a0; o[nt][1] *= a0; o[nt][2] *= a1; o[nt][3] *= a1;
        }

        // P @ V  (P fp16, identity remap S-accum -> A-frag)
        uint32_t pa[4][4];
        #pragma unroll
        for (int kt = 0; kt < 4; kt++) {
            pa[kt][0] = pack_h2(s[2*kt  ][0], s[2*kt  ][1]);
            pa[kt][1] = pack_h2(s[2*kt  ][2], s[2*kt  ][3]);
            pa[kt][2] = pack_h2(s[2*kt+1][0], s[2*kt+1][1]);
            pa[kt][3] = pack_h2(s[2*kt+1][2], s[2*kt+1][3]);
        }
        #pragma unroll
        for (int kt = 0; kt < 4; kt++)
            #pragma unroll
            for (int nt = 0; nt < 8; nt++) {
                int off = (nt*8 + g)*VST + kt*16 + tg*2;
                uint32_t b0 = *(uint32_t*)&sVt[off];
                uint32_t b1 = *(uint32_t*)&sVt[off + 8];
                mma16816(o[nt], pa[kt], b0, b1);
            }
    }

    // epilogue: O/l -> g_att[b, t, h*64+dd]
    float inv0 = 1.f / l0, inv1 = 1.f / l1;
    int r0 = qb + warp*16 + g;
    #pragma unroll
    for (int nt = 0; nt < 8; nt++) {
        int dd = nt*8 + tg*2;
        __half2 v0 = __floats2half2_rn(o[nt][0]*inv0, o[nt][1]*inv0);
        __half2 v1 = __floats2half2_rn(o[nt][2]*inv1, o[nt][3]*inv1);
        *(__half2*)&Og[((size_t)b*T_ + r0    )*C_ + h*D_ + dd] = v0;
        *(__half2*)&Og[((size_t)b*T_ + r0 + 8)*C_ + h*D_ + dd] = v1;
    }
}

// ---------------- final bias add ------------------------------------------------
__global__ void add_bias_out(const float* __restrict__ stage,
                             const float* __restrict__ bias,
                             float* __restrict__ out) {
    int i = blockIdx.x * blockDim.x + threadIdx.x;
    if (i >= (M_*C_)/4) return;
    int idx = i * 4;
    float4 v = *(const float4*)&stage[idx];
    float4 bb = *(const float4*)&bias[idx & (C_ - 1)];
    v.x += bb.x; v.y += bb.y; v.z += bb.z; v.w += bb.w;
    *(float4*)&out[idx] = v;
}

// ---------------- launch --------------------------------------------------------
extern "C" void kernel_launch(void* const* d_in, const int* in_sizes, int n_in,
                              void* d_out, int out_size) {
    const float* x      = (const float*)d_in[0];
    const float* W_kqv  = (const float*)d_in[1];
    const float* b_kqv  = (const float*)d_in[2];
    const float* W_out  = (const float*)d_in[3];
    const float* b_out  = (const float*)d_in[4];
    float*       out    = (float*)d_out;

    __half *p_xh, *p_wkqv, *p_wout, *p_q, *p_k, *p_v, *p_att;
    float *p_stage;
    cudaGetSymbolAddress((void**)&p_xh,    g_xh);
    cudaGetSymbolAddress((void**)&p_wkqv,  g_wkqv);
    cudaGetSymbolAddress((void**)&p_wout,  g_wout);
    cudaGetSymbolAddress((void**)&p_q,     g_q);
    cudaGetSymbolAddress((void**)&p_k,     g_k);
    cudaGetSymbolAddress((void**)&p_v,     g_v);
    cudaGetSymbolAddress((void**)&p_att,   g_att);
    cudaGetSymbolAddress((void**)&p_stage, g_stage);

    cudaFuncSetAttribute(gemm_fp16,
                         cudaFuncAttributeMaxDynamicSharedMemorySize, SMEM_BYTES);

    // 1) converts
    cvt4<<<(M_*C_/4 + 255)/256, 256>>>((const float4*)x,     (__half2*)p_xh,   M_*C_/4);
    cvt4<<<(C_*N1_/4 + 255)/256, 256>>>((const float4*)W_kqv, (__half2*)p_wkqv, C_*N1_/4);
    cvt4<<<(C_*C_/4 + 255)/256, 256>>>((const float4*)W_out, (__half2*)p_wout, C_*C_/4);

    // 2) kqv GEMM: [8192,1024] x [1024,3072]
    {
        dim3 grid(N1_/BN, M_/BM);    // 12 x 64
        gemm_fp16<<<grid, 256, SMEM_BYTES>>>(p_xh, p_wkqv, p_stage, N1_, C_);
    }

    // 3) bias + scatter (k,q,v order; 1/32 folded into q)
    scatter_kqv<<<(M_*N1_/2 + 255)/256, 256>>>(p_stage, b_kqv);

    // 4) attention
    {
        dim3 grid(T_/64, B_*H_);
        attn_kernel<<<grid, 128>>>(p_q, p_k, p_v, p_att);
    }

    // 5) output projection: [8192,1024] x [1024,1024]
    {
        dim3 grid(C_/BN, M_/BM);     // 4 x 64
        gemm_fp16<<<grid, 256, SMEM_BYTES>>>(p_att, p_wout, p_stage, C_, C_);
    }

    // 6) bias -> d_out
    add_bias_out<<<(M_*C_/4 + 255)/256, 256>>>(p_stage, b_out, out);

    (void)in_sizes; (void)n_in; (void)out_size;
}

// round 6
// speedup vs baseline: 2.7627x; 1.1574x over previous
#include <cuda_runtime.h>
#include <cuda_fp16.h>
#include <cstdint>

#define B_   4
#define T_   2048
#define C_   1024
#define H_   16
#define D_   64
#define M_   (B_*T_)      /* 8192 */
#define N1_  (3*C_)       /* 3072 */

// ---------------- scratch (device globals) -------------------------------------
__device__ __half g_xh   [M_*C_];
__device__ __half g_wkqvT[N1_*C_];   // [N][K] fp16
__device__ __half g_woutT[C_*C_];    // [N][K] fp16
__device__ __half g_q    [M_*C_];
__device__ __half g_k    [M_*C_];
__device__ __half g_v    [M_*C_];
__device__ __half g_att  [M_*C_];

// ---------------- PTX helpers ---------------------------------------------------
__device__ __forceinline__ void cp16(void* smem, const void* gmem) {
    uint32_t s = (uint32_t)__cvta_generic_to_shared(smem);
    asm volatile("cp.async.cg.shared.global [%0], [%1], 16;\n" :: "r"(s), "l"(gmem));
}
__device__ __forceinline__ void cp_commit() {
    asm volatile("cp.async.commit_group;\n");
}
template <int N>
__device__ __forceinline__ void cp_wait() {
    asm volatile("cp.async.wait_group %0;\n" :: "n"(N));
}
__device__ __forceinline__ void ldmx4(uint32_t r[4], uint32_t addr) {
    asm volatile("ldmatrix.sync.aligned.m8n8.x4.shared.b16 {%0,%1,%2,%3}, [%4];"
                 : "=r"(r[0]), "=r"(r[1]), "=r"(r[2]), "=r"(r[3]) : "r"(addr));
}
__device__ __forceinline__ void mma16816(float c[4], const uint32_t a[4],
                                         uint32_t b0, uint32_t b1) {
    asm volatile(
        "mma.sync.aligned.m16n8k16.row.col.f32.f16.f16.f32 "
        "{%0,%1,%2,%3}, {%4,%5,%6,%7}, {%8,%9}, {%0,%1,%2,%3};\n"
        : "+f"(c[0]), "+f"(c[1]), "+f"(c[2]), "+f"(c[3])
        : "r"(a[0]), "r"(a[1]), "r"(a[2]), "r"(a[3]), "r"(b0), "r"(b1));
}
__device__ __forceinline__ uint32_t s2u(const void* p) {
    return (uint32_t)__cvta_generic_to_shared(p);
}

// ---------------- fp32 -> fp16 convert (vectorized x4) -------------------------
__global__ void cvt4(const float4* __restrict__ in,
                     __half2* __restrict__ out, int n4) {
    int i = blockIdx.x * blockDim.x + threadIdx.x;
    if (i < n4) {
        float4 v = in[i];
        out[2*i]   = __floats2half2_rn(v.x, v.y);
        out[2*i+1] = __floats2half2_rn(v.z, v.w);
    }
}

// ---------------- fp32 [K][N] -> fp16 transposed [N][K] ------------------------
__global__ void cvt_T(const float* __restrict__ in,
                      __half* __restrict__ outT, int K, int N) {
    __shared__ float tile[32][33];
    int n0 = blockIdx.x * 32, k0 = blockIdx.y * 32;
    int tx = threadIdx.x & 31, ty = threadIdx.x >> 5;   // 256 thr: ty 0..7
    #pragma unroll
    for (int i = 0; i < 32; i += 8)
        tile[ty + i][tx] = in[(size_t)(k0 + ty + i)*N + n0 + tx];
    __syncthreads();
    #pragma unroll
    for (int i = 0; i < 32; i += 8)
        outT[(size_t)(n0 + ty + i)*K + k0 + tx] = __float2half_rn(tile[tx][ty + i]);
}

// ---------------- fused raw-mma fp16 GEMM ---------------------------------------
// C[M][N] = A[M][K] * Bt[N][K]^T, fp32 accum.
// mode 0: + bias, scatter k/q/v head-major (k,q,v thirds; q scaled 1/32)
// mode 1: + bias, fp32 row-major out
#define GBM 128
#define GBN 256
#define GBK 64
#define GSTR 72    /* half elems per row; 144B, 16B-aligned, ldmatrix conflict-free */

struct GStage {
    __half A [GBM*GSTR];
    __half Bn[GBN*GSTR];
};
#define G_SMEM_BYTES (3 * (int)sizeof(GStage))

__global__ void __launch_bounds__(256, 1)
gemm_fused(const __half* __restrict__ Ag, const __half* __restrict__ Bt,
           const float* __restrict__ bias, int K, int Nout, int mode,
           __half* __restrict__ k_out, __half* __restrict__ q_out,
           __half* __restrict__ v_out, float* __restrict__ f_out) {
    extern __shared__ __align__(128) char smem_raw[];
    GStage* stg = reinterpret_cast<GStage*>(smem_raw);

    const int tid  = threadIdx.x;
    const int warp = tid >> 5;
    const int lane = tid & 31;
    const int g    = lane >> 2;
    const int tg   = lane & 3;
    const int bm = blockIdx.y * GBM;
    const int bn = blockIdx.x * GBN;
    const int wm = (warp >> 2) * 64;
    const int wn = (warp & 3) * 64;
    const int NIT = K / GBK;

    // lane-dependent ldmatrix offsets (bytes)
    const int grp = lane >> 3, lr = lane & 7;
    const int rowOffA = ((grp & 1)*8 + lr) * (GSTR*2) + (grp >> 1)*16;
    const int rowOffB = ((grp >> 1)*8 + lr) * (GSTR*2) + (grp & 1)*16;

    auto load_stage = [&](GStage& S, int k0) {
        #pragma unroll
        for (int t = 0; t < 4; t++) {               // A: 128 rows x 8 cp16
            int id = tid + 256*t;
            int r = id >> 3, c = (id & 7) * 8;
            cp16(&S.A[r*GSTR + c], &Ag[(size_t)(bm + r)*K + k0 + c]);
        }
        #pragma unroll
        for (int t = 0; t < 8; t++) {               // B: 256 rows x 8 cp16
            int id = tid + 256*t;
            int r = id >> 3, c = (id & 7) * 8;
            cp16(&S.Bn[r*GSTR + c], &Bt[(size_t)(bn + r)*K + k0 + c]);
        }
        cp_commit();
    };

    float c[4][8][4];
    #pragma unroll
    for (int i = 0; i < 4; i++)
        #pragma unroll
        for (int j = 0; j < 8; j++)
            c[i][j][0] = c[i][j][1] = c[i][j][2] = c[i][j][3] = 0.f;

    load_stage(stg[0], 0);
    load_stage(stg[1], GBK);

    for (int it = 0; it < NIT; it++) {
        if (it == NIT - 1) cp_wait<0>(); else cp_wait<1>();
        __syncthreads();
        if (it + 2 < NIT) load_stage(stg[(it + 2) % 3], (it + 2) * GBK);

        GStage& S = stg[it % 3];
        const uint32_t baseA = s2u(&S.A[0])  + wm*(GSTR*2) + rowOffA;
        const uint32_t baseB = s2u(&S.Bn[0]) + wn*(GSTR*2) + rowOffB;

        #pragma unroll
        for (int kk = 0; kk < GBK; kk += 16) {
            uint32_t a[4][4], b[4][4];
            #pragma unroll
            for (int mt = 0; mt < 4; mt++)
                ldmx4(a[mt], baseA + mt*16*(GSTR*2) + kk*2);
            #pragma unroll
            for (int nt2 = 0; nt2 < 4; nt2++)
                ldmx4(b[nt2], baseB + nt2*16*(GSTR*2) + kk*2);
            #pragma unroll
            for (int mt = 0; mt < 4; mt++)
                #pragma unroll
                for (int nt = 0; nt < 8; nt++)
                    mma16816(c[mt][nt], a[mt],
                             b[nt >> 1][(nt & 1)*2], b[nt >> 1][(nt & 1)*2 + 1]);
        }
    }

    // -------- fused epilogue (fragment mapping: c0,c1 -> row g cols tg*2,+1;
    //          c2,c3 -> row g+8 same cols) --------
    #pragma unroll
    for (int nt = 0; nt < 8; nt++) {
        const int n = bn + wn + nt*8 + tg*2;
        const float b0f = bias[n], b1f = bias[n + 1];
        if (mode == 0) {
            const int third = n >> 10;
            const int cc = n & 1023;
            const int hh = cc >> 6, dd = cc & 63;
            __half* dst_arr = (third == 0) ? k_out : (third == 1) ? q_out : v_out;
            const float scale = (third == 1) ? (1.0f/32.0f) : 1.0f;
            #pragma unroll
            for (int mt = 0; mt < 4; mt++) {
                #pragma unroll
                for (int half_ = 0; half_ < 2; half_++) {
                    int m = bm + wm + mt*16 + g + half_*8;
                    int bq = m >> 11, tq = m & (T_ - 1);
                    size_t dst = (((size_t)(bq*H_ + hh))*T_ + tq)*D_ + dd;
                    float v0 = (c[mt][nt][half_*2]     + b0f) * scale;
                    float v1 = (c[mt][nt][half_*2 + 1] + b1f) * scale;
                    *(__half2*)&dst_arr[dst] = __floats2half2_rn(v0, v1);
                }
            }
        } else {
            #pragma unroll
            for (int mt = 0; mt < 4; mt++) {
                #pragma unroll
                for (int half_ = 0; half_ < 2; half_++) {
                    int m = bm + wm + mt*16 + g + half_*8;
                    float2 v;
                    v.x = c[mt][nt][half_*2]     + b0f;
                    v.y = c[mt][nt][half_*2 + 1] + b1f;
                    *(float2*)&f_out[(size_t)m*Nout + n] = v;
                }
            }
        }
    }
}

// ---------------- attention (FA-2, mma.m16n8k16.f16) ---------------------------
__device__ __forceinline__ uint32_t pack_h2(float x, float y) {
    __half2 t = __floats2half2_rn(x, y);
    return *(uint32_t*)&t;
}

#define KST 72
#define VST 68

__global__ void __launch_bounds__(128)
attn_kernel(const __half* __restrict__ Qg,
            const __half* __restrict__ Kg,
            const __half* __restrict__ Vg,
            __half* __restrict__ Og) {
    __shared__ __align__(16) __half sQ [64*KST];
    __shared__ __align__(16) __half sK [64*KST];
    __shared__ __align__(16) __half sVt[64*VST];

    const int qt  = blockIdx.x;
    const int bh  = blockIdx.y;
    const int b   = bh >> 4, h = bh & 15;
    const int tid = threadIdx.x;
    const int warp = tid >> 5, lane = tid & 31;
    const int g  = lane >> 2;
    const int tg = lane & 3;

    const __half* Qb = Qg + (size_t)bh * T_ * D_;
    const __half* Kb = Kg + (size_t)bh * T_ * D_;
    const __half* Vb = Vg + (size_t)bh * T_ * D_;
    const int qb = qt * 64;

    #pragma unroll
    for (int t = 0; t < 4; t++) {
        int idx = tid + t*128;
        int r = idx >> 3, c = (idx & 7) * 8;
        *(uint4*)&sQ[r*KST + c] = *(const uint4*)&Qb[(size_t)(qb + r)*D_ + c];
    }
    __syncthreads();

    uint32_t qa[4][4];
    {
        int r0 = warp*16 + g;
        #pragma unroll
        for (int kk = 0; kk < 4; kk++) {
            int cb = kk*16 + tg*2;
            qa[kk][0] = *(uint32_t*)&sQ[r0*KST + cb];
            qa[kk][1] = *(uint32_t*)&sQ[(r0+8)*KST + cb];
            qa[kk][2] = *(uint32_t*)&sQ[r0*KST + cb + 8];
            qa[kk][3] = *(uint32_t*)&sQ[(r0+8)*KST + cb + 8];
        }
    }

    float o[8][4];
    #pragma unroll
    for (int i = 0; i < 8; i++) { o[i][0]=o[i][1]=o[i][2]=o[i][3]=0.f; }
    float m0 = -1e30f, m1 = -1e30f, l0 = 0.f, l1 = 0.f;

    const int ntiles = qt + 1;
    for (int it = 0; it < ntiles; it++) {
        const int kb = it * 64;
        __syncthreads();
        #pragma unroll
        for (int t = 0; t < 4; t++) {                     // K tile 64x64
            int idx = tid + t*128;
            int r = idx >> 3, c = (idx & 7) * 8;
            *(uint4*)&sK[r*KST + c] = *(const uint4*)&Kb[(size_t)(kb + r)*D_ + c];
        }
        #pragma unroll
        for (int t = 0; t < 4; t++) {                     // V tile, transposed
            int idx = tid + t*128;
            int r = idx >> 3, c0 = (idx & 7) * 8;
            uint4 vv = *(const uint4*)&Vb[(size_t)(kb + r)*D_ + c0];
            __half tmp[8];
            *(uint4*)tmp = vv;
            #pragma unroll
            for (int i = 0; i < 8; i++) sVt[(c0 + i)*VST + r] = tmp[i];
        }
        __syncthreads();

        float s[8][4];
        #pragma unroll
        for (int nt = 0; nt < 8; nt++) { s[nt][0]=s[nt][1]=s[nt][2]=s[nt][3]=0.f; }
        #pragma unroll
        for (int kk = 0; kk < 4; kk++)
            #pragma unroll
            for (int nt = 0; nt < 8; nt++) {
                uint32_t b0 = *(uint32_t*)&sK[(nt*8 + g)*KST + kk*16 + tg*2];
                uint32_t b1 = *(uint32_t*)&sK[(nt*8 + g)*KST + kk*16 + tg*2 + 8];
                mma16816(s[nt], qa[kk], b0, b1);
            }

        if (it == ntiles - 1) {   // causal mask on diagonal tile
            int qg0 = qb + warp*16 + g;
            #pragma unroll
            for (int nt = 0; nt < 8; nt++) {
                int kg = kb + nt*8 + tg*2;
                if (kg     > qg0    ) s[nt][0] = -1e30f;
                if (kg + 1 > qg0    ) s[nt][1] = -1e30f;
                if (kg     > qg0 + 8) s[nt][2] = -1e30f;
                if (kg + 1 > qg0 + 8) s[nt][3] = -1e30f;
            }
        }

        float mx0 = -1e30f, mx1 = -1e30f;
        #pragma unroll
        for (int nt = 0; nt < 8; nt++) {
            mx0 = fmaxf(mx0, fmaxf(s[nt][0], s[nt][1]));
            mx1 = fmaxf(mx1, fmaxf(s[nt][2], s[nt][3]));
        }
        #pragma unroll
        for (int off = 1; off < 4; off <<= 1) {
            mx0 = fmaxf(mx0, __shfl_xor_sync(0xffffffffu, mx0, off));
            mx1 = fmaxf(mx1, __shfl_xor_sync(0xffffffffu, mx1, off));
        }
        float nm0 = fmaxf(m0, mx0), nm1 = fmaxf(m1, mx1);
        float a0 = __expf(m0 - nm0), a1 = __expf(m1 - nm1);
        float sum0 = 0.f, sum1 = 0.f;
        #pragma unroll
        for (int nt = 0; nt < 8; nt++) {
            s[nt][0] = __expf(s[nt][0] - nm0);
            s[nt][1] = __expf(s[nt][1] - nm0);
            s[nt][2] = __expf(s[nt][2] - nm1);
            s[nt][3] = __expf(s[nt][3] - nm1);
            sum0 += s[nt][0] + s[nt][1];
            sum1 += s[nt][2] + s[nt][3];
        }
        #pragma unroll
        for (int off = 1; off < 4; off <<= 1) {
            sum0 += __shfl_xor_sync(0xffffffffu, sum0, off);
            sum1 += __shfl_xor_sync(0xffffffffu, sum1, off);
        }
        l0 = l0*a0 + sum0;  l1 = l1*a1 + sum1;
        m0 = nm0;           m1 = nm1;
        #pragma unroll
        for (int nt = 0; nt < 8; nt++) {
            o[nt][0] *= a0; o[nt][1] *= a0; o[nt][2] *= a1; o[nt][3] *= a1;
        }

        uint32_t pa[4][4];
        #pragma unroll
        for (int kt = 0; kt < 4; kt++) {
            pa[kt][0] = pack_h2(s[2*kt  ][0], s[2*kt  ][1]);
            pa[kt][1] = pack_h2(s[2*kt  ][2], s[2*kt  ][3]);
            pa[kt][2] = pack_h2(s[2*kt+1][0], s[2*kt+1][1]);
            pa[kt][3] = pack_h2(s[2*kt+1][2], s[2*kt+1][3]);
        }
        #pragma unroll
        for (int kt = 0; kt < 4; kt++)
            #pragma unroll
            for (int nt = 0; nt < 8; nt++) {
                int off = (nt*8 + g)*VST + kt*16 + tg*2;
                uint32_t b0 = *(uint32_t*)&sVt[off];
                uint32_t b1 = *(uint32_t*)&sVt[off + 8];
                mma16816(o[nt], pa[kt], b0, b1);
            }
    }

    float inv0 = 1.f / l0, inv1 = 1.f / l1;
    int r0 = qb + warp*16 + g;
    #pragma unroll
    for (int nt = 0; nt < 8; nt++) {
        int dd = nt*8 + tg*2;
        __half2 v0 = __floats2half2_rn(o[nt][0]*inv0, o[nt][1]*inv0);
        __half2 v1 = __floats2half2_rn(o[nt][2]*inv1, o[nt][3]*inv1);
        *(__half2*)&Og[((size_t)b*T_ + r0    )*C_ + h*D_ + dd] = v0;
        *(__half2*)&Og[((size_t)b*T_ + r0 + 8)*C_ + h*D_ + dd] = v1;
    }
}

// ---------------- launch --------------------------------------------------------
extern "C" void kernel_launch(void* const* d_in, const int* in_sizes, int n_in,
                              void* d_out, int out_size) {
    const float* x      = (const float*)d_in[0];
    const float* W_kqv  = (const float*)d_in[1];
    const float* b_kqv  = (const float*)d_in[2];
    const float* W_out  = (const float*)d_in[3];
    const float* b_out  = (const float*)d_in[4];
    float*       out    = (float*)d_out;

    __half *p_xh, *p_wkT, *p_woT, *p_q, *p_k, *p_v, *p_att;
    cudaGetSymbolAddress((void**)&p_xh,  g_xh);
    cudaGetSymbolAddress((void**)&p_wkT, g_wkqvT);
    cudaGetSymbolAddress((void**)&p_woT, g_woutT);
    cudaGetSymbolAddress((void**)&p_q,   g_q);
    cudaGetSymbolAddress((void**)&p_k,   g_k);
    cudaGetSymbolAddress((void**)&p_v,   g_v);
    cudaGetSymbolAddress((void**)&p_att, g_att);

    cudaFuncSetAttribute(gemm_fused,
                         cudaFuncAttributeMaxDynamicSharedMemorySize, G_SMEM_BYTES);

    // 1) converts: x -> fp16; weights -> fp16 transposed [N][K]
    cvt4<<<(M_*C_/4 + 255)/256, 256>>>((const float4*)x, (__half2*)p_xh, M_*C_/4);
    {
        dim3 g1(N1_/32, C_/32);
        cvt_T<<<g1, 256>>>(W_kqv, p_wkT, C_, N1_);
        dim3 g2(C_/32, C_/32);
        cvt_T<<<g2, 256>>>(W_out, p_woT, C_, C_);
    }

    // 2) kqv GEMM + fused bias/scatter: [8192,1024] x [1024,3072]
    {
        dim3 grid(N1_/GBN, M_/GBM);   // 12 x 64
        gemm_fused<<<grid, 256, G_SMEM_BYTES>>>(p_xh, p_wkT, b_kqv, C_, N1_, 0,
                                                p_k, p_q, p_v, nullptr);
    }

    // 3) attention
    {
        dim3 grid(T_/64, B_*H_);
        attn_kernel<<<grid, 128>>>(p_q, p_k, p_v, p_att);
    }

    // 4) output projection + fused bias -> d_out: [8192,1024] x [1024,1024]
    {
        dim3 grid(C_/GBN, M_/GBM);    // 4 x 64
        gemm_fused<<<grid, 256, G_SMEM_BYTES>>>(p_att, p_woT, b_out, C_, C_, 1,
                                                nullptr, nullptr, nullptr, out);
    }

    (void)in_sizes; (void)n_in; (void)out_size;
}

// round 7
// speedup vs baseline: 2.9672x; 1.0740x over previous
#include <cuda_runtime.h>
#include <cuda_fp16.h>
#include <cstdint>

#define B_   4
#define T_   2048
#define C_   1024
#define H_   16
#define D_   64
#define M_   (B_*T_)      /* 8192 */
#define N1_  (3*C_)       /* 3072 */

// ---------------- scratch (device globals) -------------------------------------
__device__ __half g_xh   [M_*C_];
__device__ __half g_wkqvT[N1_*C_];   // [N][K] fp16
__device__ __half g_woutT[C_*C_];    // [N][K] fp16
__device__ __half g_q    [M_*C_];
__device__ __half g_k    [M_*C_];
__device__ __half g_v    [M_*C_];
__device__ __half g_att  [M_*C_];

// ---------------- PTX helpers ---------------------------------------------------
__device__ __forceinline__ void cp16(void* smem, const void* gmem) {
    uint32_t s = (uint32_t)__cvta_generic_to_shared(smem);
    asm volatile("cp.async.cg.shared.global [%0], [%1], 16;\n" :: "r"(s), "l"(gmem));
}
__device__ __forceinline__ void cp_commit() {
    asm volatile("cp.async.commit_group;\n");
}
template <int N>
__device__ __forceinline__ void cp_wait() {
    asm volatile("cp.async.wait_group %0;\n" :: "n"(N));
}
__device__ __forceinline__ void ldmx4(uint32_t r[4], uint32_t addr) {
    asm volatile("ldmatrix.sync.aligned.m8n8.x4.shared.b16 {%0,%1,%2,%3}, [%4];"
                 : "=r"(r[0]), "=r"(r[1]), "=r"(r[2]), "=r"(r[3]) : "r"(addr));
}
__device__ __forceinline__ void mma16816(float c[4], const uint32_t a[4],
                                         uint32_t b0, uint32_t b1) {
    asm volatile(
        "mma.sync.aligned.m16n8k16.row.col.f32.f16.f16.f32 "
        "{%0,%1,%2,%3}, {%4,%5,%6,%7}, {%8,%9}, {%0,%1,%2,%3};\n"
        : "+f"(c[0]), "+f"(c[1]), "+f"(c[2]), "+f"(c[3])
        : "r"(a[0]), "r"(a[1]), "r"(a[2]), "r"(a[3]), "r"(b0), "r"(b1));
}
__device__ __forceinline__ uint32_t s2u(const void* p) {
    return (uint32_t)__cvta_generic_to_shared(p);
}
__device__ __forceinline__ uint32_t pack_h2(float x, float y) {
    __half2 t = __floats2half2_rn(x, y);
    return *(uint32_t*)&t;
}

// ---------------- fp32 -> fp16 convert (vectorized x4) -------------------------
__global__ void cvt4(const float4* __restrict__ in,
                     __half2* __restrict__ out, int n4) {
    int i = blockIdx.x * blockDim.x + threadIdx.x;
    if (i < n4) {
        float4 v = in[i];
        out[2*i]   = __floats2half2_rn(v.x, v.y);
        out[2*i+1] = __floats2half2_rn(v.z, v.w);
    }
}

// ---------------- fp32 [K][N] -> fp16 transposed [N][K] ------------------------
__global__ void cvt_T(const float* __restrict__ in,
                      __half* __restrict__ outT, int K, int N) {
    __shared__ float tile[32][33];
    int n0 = blockIdx.x * 32, k0 = blockIdx.y * 32;
    int tx = threadIdx.x & 31, ty = threadIdx.x >> 5;   // 256 thr: ty 0..7
    #pragma unroll
    for (int i = 0; i < 32; i += 8)
        tile[ty + i][tx] = in[(size_t)(k0 + ty + i)*N + n0 + tx];
    __syncthreads();
    #pragma unroll
    for (int i = 0; i < 32; i += 8)
        outT[(size_t)(n0 + ty + i)*K + k0 + tx] = __float2half_rn(tile[tx][ty + i]);
}

// ---------------- fused raw-mma fp16 GEMM (unchanged from R6) -------------------
#define GBM 128
#define GBN 256
#define GBK 64
#define GSTR 72

struct GStage {
    __half A [GBM*GSTR];
    __half Bn[GBN*GSTR];
};
#define G_SMEM_BYTES (3 * (int)sizeof(GStage))

__global__ void __launch_bounds__(256, 1)
gemm_fused(const __half* __restrict__ Ag, const __half* __restrict__ Bt,
           const float* __restrict__ bias, int K, int Nout, int mode,
           __half* __restrict__ k_out, __half* __restrict__ q_out,
           __half* __restrict__ v_out, float* __restrict__ f_out) {
    extern __shared__ __align__(128) char smem_raw[];
    GStage* stg = reinterpret_cast<GStage*>(smem_raw);

    const int tid  = threadIdx.x;
    const int warp = tid >> 5;
    const int lane = tid & 31;
    const int g    = lane >> 2;
    const int tg   = lane & 3;
    const int bm = blockIdx.y * GBM;
    const int bn = blockIdx.x * GBN;
    const int wm = (warp >> 2) * 64;
    const int wn = (warp & 3) * 64;
    const int NIT = K / GBK;

    const int grp = lane >> 3, lr = lane & 7;
    const int rowOffA = ((grp & 1)*8 + lr) * (GSTR*2) + (grp >> 1)*16;
    const int rowOffB = ((grp >> 1)*8 + lr) * (GSTR*2) + (grp & 1)*16;

    auto load_stage = [&](GStage& S, int k0) {
        #pragma unroll
        for (int t = 0; t < 4; t++) {
            int id = tid + 256*t;
            int r = id >> 3, c = (id & 7) * 8;
            cp16(&S.A[r*GSTR + c], &Ag[(size_t)(bm + r)*K + k0 + c]);
        }
        #pragma unroll
        for (int t = 0; t < 8; t++) {
            int id = tid + 256*t;
            int r = id >> 3, c = (id & 7) * 8;
            cp16(&S.Bn[r*GSTR + c], &Bt[(size_t)(bn + r)*K + k0 + c]);
        }
        cp_commit();
    };

    float c[4][8][4];
    #pragma unroll
    for (int i = 0; i < 4; i++)
        #pragma unroll
        for (int j = 0; j < 8; j++)
            c[i][j][0] = c[i][j][1] = c[i][j][2] = c[i][j][3] = 0.f;

    load_stage(stg[0], 0);
    load_stage(stg[1], GBK);

    for (int it = 0; it < NIT; it++) {
        if (it == NIT - 1) cp_wait<0>(); else cp_wait<1>();
        __syncthreads();
        if (it + 2 < NIT) load_stage(stg[(it + 2) % 3], (it + 2) * GBK);

        GStage& S = stg[it % 3];
        const uint32_t baseA = s2u(&S.A[0])  + wm*(GSTR*2) + rowOffA;
        const uint32_t baseB = s2u(&S.Bn[0]) + wn*(GSTR*2) + rowOffB;

        #pragma unroll
        for (int kk = 0; kk < GBK; kk += 16) {
            uint32_t a[4][4], b[4][4];
            #pragma unroll
            for (int mt = 0; mt < 4; mt++)
                ldmx4(a[mt], baseA + mt*16*(GSTR*2) + kk*2);
            #pragma unroll
            for (int nt2 = 0; nt2 < 4; nt2++)
                ldmx4(b[nt2], baseB + nt2*16*(GSTR*2) + kk*2);
            #pragma unroll
            for (int mt = 0; mt < 4; mt++)
                #pragma unroll
                for (int nt = 0; nt < 8; nt++)
                    mma16816(c[mt][nt], a[mt],
                             b[nt >> 1][(nt & 1)*2], b[nt >> 1][(nt & 1)*2 + 1]);
        }
    }

    #pragma unroll
    for (int nt = 0; nt < 8; nt++) {
        const int n = bn + wn + nt*8 + tg*2;
        const float b0f = bias[n], b1f = bias[n + 1];
        if (mode == 0) {
            const int third = n >> 10;
            const int cc = n & 1023;
            const int hh = cc >> 6, dd = cc & 63;
            __half* dst_arr = (third == 0) ? k_out : (third == 1) ? q_out : v_out;
            const float scale = (third == 1) ? (1.0f/32.0f) : 1.0f;
            #pragma unroll
            for (int mt = 0; mt < 4; mt++) {
                #pragma unroll
                for (int half_ = 0; half_ < 2; half_++) {
                    int m = bm + wm + mt*16 + g + half_*8;
                    int bq = m >> 11, tq = m & (T_ - 1);
                    size_t dst = (((size_t)(bq*H_ + hh))*T_ + tq)*D_ + dd;
                    float v0 = (c[mt][nt][half_*2]     + b0f) * scale;
                    float v1 = (c[mt][nt][half_*2 + 1] + b1f) * scale;
                    *(__half2*)&dst_arr[dst] = __floats2half2_rn(v0, v1);
                }
            }
        } else {
            #pragma unroll
            for (int mt = 0; mt < 4; mt++) {
                #pragma unroll
                for (int half_ = 0; half_ < 2; half_++) {
                    int m = bm + wm + mt*16 + g + half_*8;
                    float2 v;
                    v.x = c[mt][nt][half_*2]     + b0f;
                    v.y = c[mt][nt][half_*2 + 1] + b1f;
                    *(float2*)&f_out[(size_t)m*Nout + n] = v;
                }
            }
        }
    }
}

// ---------------- attention v2: 8 warps, 128-row q tile, async K, causal skip ---
#define KST 72
#define VST 68
// dynamic smem layout: sQ[128*KST] | sK[2][64*KST] | sVt[2][64*VST]
#define ATT_SQ_ELEMS   (128*KST)
#define ATT_SK_ELEMS   (64*KST)
#define ATT_SV_ELEMS   (64*VST)
#define ATT_SMEM_BYTES ((ATT_SQ_ELEMS + 2*ATT_SK_ELEMS + 2*ATT_SV_ELEMS) * 2)

__global__ void __launch_bounds__(256)
attn_kernel(const __half* __restrict__ Qg,
            const __half* __restrict__ Kg,
            const __half* __restrict__ Vg,
            __half* __restrict__ Og) {
    extern __shared__ __align__(16) __half asmem[];
    __half* sQ  = asmem;
    __half* sK  = sQ + ATT_SQ_ELEMS;
    __half* sVt = sK + 2*ATT_SK_ELEMS;

    const int qtile = gridDim.x - 1 - blockIdx.x;   // heavy tiles first
    const int qb  = qtile * 128;
    const int bh  = blockIdx.y;
    const int b   = bh >> 4, h = bh & 15;
    const int tid = threadIdx.x;
    const int warp = tid >> 5, lane = tid & 31;
    const int g  = lane >> 2;
    const int tg = lane & 3;

    const __half* Qb = Qg + (size_t)bh * T_ * D_;
    const __half* Kb = Kg + (size_t)bh * T_ * D_;
    const __half* Vb = Vg + (size_t)bh * T_ * D_;

    // Q tile -> smem (128x64); 256 threads x 4 uint4
    #pragma unroll
    for (int t = 0; t < 4; t++) {
        int idx = tid + t*256;
        int r = idx >> 3, c = (idx & 7) * 8;
        *(uint4*)&sQ[r*KST + c] = *(const uint4*)&Qb[(size_t)(qb + r)*D_ + c];
    }
    __syncthreads();

    // per-warp Q fragments: rows warp*16 + g (+8)
    uint32_t qa[4][4];
    {
        int r0 = warp*16 + g;
        #pragma unroll
        for (int kk = 0; kk < 4; kk++) {
            int cb = kk*16 + tg*2;
            qa[kk][0] = *(uint32_t*)&sQ[r0*KST + cb];
            qa[kk][1] = *(uint32_t*)&sQ[(r0+8)*KST + cb];
            qa[kk][2] = *(uint32_t*)&sQ[r0*KST + cb + 8];
            qa[kk][3] = *(uint32_t*)&sQ[(r0+8)*KST + cb + 8];
        }
    }

    float o[8][4];
    #pragma unroll
    for (int i = 0; i < 8; i++) { o[i][0]=o[i][1]=o[i][2]=o[i][3]=0.f; }
    float m0 = -1e30f, m1 = -1e30f, l0 = 0.f, l1 = 0.f;

    const int ntiles = 2*qtile + 2;
    const int vr = tid >> 3, vc0 = (tid & 7) * 8;   // V load coords (t adds +32 rows)

    // preload stage 0: K via cp.async, V via LDG + transposed STS
    {
        #pragma unroll
        for (int t = 0; t < 2; t++) {
            int r = vr + t*32;
            cp16(&sK[r*KST + vc0], &Kb[(size_t)r*D_ + vc0]);
        }
        cp_commit();
        #pragma unroll
        for (int t = 0; t < 2; t++) {
            int r = vr + t*32;
            uint4 vv = *(const uint4*)&Vb[(size_t)r*D_ + vc0];
            __half tmp[8];
            *(uint4*)tmp = vv;
            #pragma unroll
            for (int i = 0; i < 8; i++) sVt[(vc0 + i)*VST + r] = tmp[i];
        }
    }

    for (int it = 0; it < ntiles; it++) {
        const int kb = it * 64;
        const int stage = it & 1;
        cp_wait<0>();        // K(it) arrived (issued one iteration ago)
        __syncthreads();     // V(it) STS visible; all warps done with stage^1

        uint4 vreg[2];
        const bool pre = (it + 1 < ntiles);
        if (pre) {           // prefetch K(it+1), LDG V(it+1)
            const int kb2 = kb + 64;
            __half* sKn = sK + (stage ^ 1)*ATT_SK_ELEMS;
            #pragma unroll
            for (int t = 0; t < 2; t++) {
                int r = vr + t*32;
                cp16(&sKn[r*KST + vc0], &Kb[(size_t)(kb2 + r)*D_ + vc0]);
            }
            cp_commit();
            #pragma unroll
            for (int t = 0; t < 2; t++) {
                int r = vr + t*32;
                vreg[t] = *(const uint4*)&Vb[(size_t)(kb2 + r)*D_ + vc0];
            }
        }

        // per-warp causal skip: all of this warp's rows precede this k tile
        if (kb <= qb + warp*16 + 15) {
            const __half* sKs  = sK  + stage*ATT_SK_ELEMS;
            const __half* sVts = sVt + stage*ATT_SV_ELEMS;

            float s[8][4];
            #pragma unroll
            for (int nt = 0; nt < 8; nt++) { s[nt][0]=s[nt][1]=s[nt][2]=s[nt][3]=0.f; }
            #pragma unroll
            for (int kk = 0; kk < 4; kk++)
                #pragma unroll
                for (int nt = 0; nt < 8; nt++) {
                    uint32_t b0 = *(uint32_t*)&sKs[(nt*8 + g)*KST + kk*16 + tg*2];
                    uint32_t b1 = *(uint32_t*)&sKs[(nt*8 + g)*KST + kk*16 + tg*2 + 8];
                    mma16816(s[nt], qa[kk], b0, b1);
                }

            if (kb + 63 > qb + warp*16) {     // tile overlaps diagonal for this warp
                int qg0 = qb + warp*16 + g;
                #pragma unroll
                for (int nt = 0; nt < 8; nt++) {
                    int kg = kb + nt*8 + tg*2;
                    if (kg     > qg0    ) s[nt][0] = -1e30f;
                    if (kg + 1 > qg0    ) s[nt][1] = -1e30f;
                    if (kg     > qg0 + 8) s[nt][2] = -1e30f;
                    if (kg + 1 > qg0 + 8) s[nt][3] = -1e30f;
                }
            }

            // online softmax
            float mx0 = -1e30f, mx1 = -1e30f;
            #pragma unroll
            for (int nt = 0; nt < 8; nt++) {
                mx0 = fmaxf(mx0, fmaxf(s[nt][0], s[nt][1]));
                mx1 = fmaxf(mx1, fmaxf(s[nt][2], s[nt][3]));
            }
            #pragma unroll
            for (int off = 1; off < 4; off <<= 1) {
                mx0 = fmaxf(mx0, __shfl_xor_sync(0xffffffffu, mx0, off));
                mx1 = fmaxf(mx1, __shfl_xor_sync(0xffffffffu, mx1, off));
            }
            float nm0 = fmaxf(m0, mx0), nm1 = fmaxf(m1, mx1);
            float a0 = __expf(m0 - nm0), a1 = __expf(m1 - nm1);
            float sum0 = 0.f, sum1 = 0.f;
            #pragma unroll
            for (int nt = 0; nt < 8; nt++) {
                s[nt][0] = __expf(s[nt][0] - nm0);
                s[nt][1] = __expf(s[nt][1] - nm0);
                s[nt][2] = __expf(s[nt][2] - nm1);
                s[nt][3] = __expf(s[nt][3] - nm1);
                sum0 += s[nt][0] + s[nt][1];
                sum1 += s[nt][2] + s[nt][3];
            }
            #pragma unroll
            for (int off = 1; off < 4; off <<= 1) {
                sum0 += __shfl_xor_sync(0xffffffffu, sum0, off);
                sum1 += __shfl_xor_sync(0xffffffffu, sum1, off);
            }
            l0 = l0*a0 + sum0;  l1 = l1*a1 + sum1;
            m0 = nm0;           m1 = nm1;
            #pragma unroll
            for (int nt = 0; nt < 8; nt++) {
                o[nt][0] *= a0; o[nt][1] *= a0; o[nt][2] *= a1; o[nt][3] *= a1;
            }

            // P @ V
            uint32_t pa[4][4];
            #pragma unroll
            for (int kt = 0; kt < 4; kt++) {
                pa[kt][0] = pack_h2(s[2*kt  ][0], s[2*kt  ][1]);
                pa[kt][1] = pack_h2(s[2*kt  ][2], s[2*kt  ][3]);
                pa[kt][2] = pack_h2(s[2*kt+1][0], s[2*kt+1][1]);
                pa[kt][3] = pack_h2(s[2*kt+1][2], s[2*kt+1][3]);
            }
            #pragma unroll
            for (int kt = 0; kt < 4; kt++)
                #pragma unroll
                for (int nt = 0; nt < 8; nt++) {
                    int off = (nt*8 + g)*VST + kt*16 + tg*2;
                    uint32_t b0 = *(uint32_t*)&sVts[off];
                    uint32_t b1 = *(uint32_t*)&sVts[off + 8];
                    mma16816(o[nt], pa[kt], b0, b1);
                }
        }

        if (pre) {           // store V(it+1) into the other stage
            __half* sVtn = sVt + (stage ^ 1)*ATT_SV_ELEMS;
            #pragma unroll
            for (int t = 0; t < 2; t++) {
                int r = vr + t*32;
                __half tmp[8];
                *(uint4*)tmp = vreg[t];
                #pragma unroll
                for (int i = 0; i < 8; i++) sVtn[(vc0 + i)*VST + r] = tmp[i];
            }
        }
    }

    // epilogue: O/l -> g_att[b, t, h*64+dd]
    float inv0 = 1.f / l0, inv1 = 1.f / l1;
    int r0 = qb + warp*16 + g;
    #pragma unroll
    for (int nt = 0; nt < 8; nt++) {
        int dd = nt*8 + tg*2;
        __half2 v0 = __floats2half2_rn(o[nt][0]*inv0, o[nt][1]*inv0);
        __half2 v1 = __floats2half2_rn(o[nt][2]*inv1, o[nt][3]*inv1);
        *(__half2*)&Og[((size_t)b*T_ + r0    )*C_ + h*D_ + dd] = v0;
        *(__half2*)&Og[((size_t)b*T_ + r0 + 8)*C_ + h*D_ + dd] = v1;
    }
}

// ---------------- launch --------------------------------------------------------
extern "C" void kernel_launch(void* const* d_in, const int* in_sizes, int n_in,
                              void* d_out, int out_size) {
    const float* x      = (const float*)d_in[0];
    const float* W_kqv  = (const float*)d_in[1];
    const float* b_kqv  = (const float*)d_in[2];
    const float* W_out  = (const float*)d_in[3];
    const float* b_out  = (const float*)d_in[4];
    float*       out    = (float*)d_out;

    __half *p_xh, *p_wkT, *p_woT, *p_q, *p_k, *p_v, *p_att;
    cudaGetSymbolAddress((void**)&p_xh,  g_xh);
    cudaGetSymbolAddress((void**)&p_wkT, g_wkqvT);
    cudaGetSymbolAddress((void**)&p_woT, g_woutT);
    cudaGetSymbolAddress((void**)&p_q,   g_q);
    cudaGetSymbolAddress((void**)&p_k,   g_k);
    cudaGetSymbolAddress((void**)&p_v,   g_v);
    cudaGetSymbolAddress((void**)&p_att, g_att);

    cudaFuncSetAttribute(gemm_fused,
                         cudaFuncAttributeMaxDynamicSharedMemorySize, G_SMEM_BYTES);
    cudaFuncSetAttribute(attn_kernel,
                         cudaFuncAttributeMaxDynamicSharedMemorySize, ATT_SMEM_BYTES);

    // 1) converts
    cvt4<<<(M_*C_/4 + 255)/256, 256>>>((const float4*)x, (__half2*)p_xh, M_*C_/4);
    {
        dim3 g1(N1_/32, C_/32);
        cvt_T<<<g1, 256>>>(W_kqv, p_wkT, C_, N1_);
        dim3 g2(C_/32, C_/32);
        cvt_T<<<g2, 256>>>(W_out, p_woT, C_, C_);
    }

    // 2) kqv GEMM + fused bias/scatter
    {
        dim3 grid(N1_/GBN, M_/GBM);
        gemm_fused<<<grid, 256, G_SMEM_BYTES>>>(p_xh, p_wkT, b_kqv, C_, N1_, 0,
                                                p_k, p_q, p_v, nullptr);
    }

    // 3) attention (128-row q tiles, 8 warps)
    {
        dim3 grid(T_/128, B_*H_);
        attn_kernel<<<grid, 256, ATT_SMEM_BYTES>>>(p_q, p_k, p_v, p_att);
    }

    // 4) output projection + fused bias -> d_out
    {
        dim3 grid(C_/GBN, M_/GBM);
        gemm_fused<<<grid, 256, G_SMEM_BYTES>>>(p_att, p_woT, b_out, C_, C_, 1,
                                                nullptr, nullptr, nullptr, out);
    }

    (void)in_sizes; (void)n_in; (void)out_size;
}